// round 10
// baseline (speedup 1.0000x reference)
#include <cuda_runtime.h>
#include <cuda_bf16.h>
#include <math_constants.h>
#include <cstdint>

// Problem constants
#define Bq   16
#define Nq   4096
#define Dq   128
#define Sq   1024
#define Kq   16
#define CIN  131            // 3 + D
#define KT1  192            // layer-1 K padded (6 chunks of 32)
#define KT2  256            // layer-2 K (8 chunks of 32)
#define NT   (Bq*Sq*Kq)     // 262144 tokens
#define NTILES (NT/128)     // 2048 n-tiles
#define OUT_XYZ (Bq*Sq*3)

typedef __nv_bfloat16 bf16;

// ---------------- static device scratch -------------------------------------
__device__ float d_newxyz[Bq*Sq*3];
__device__ __align__(16) bf16 d_W1hi[256*KT1], d_W1lo[256*KT1];
__device__ __align__(16) bf16 d_W2hi[256*KT2], d_W2lo[256*KT2];
__device__ __align__(16) bf16 d_Fhi[(size_t)NT*KT1], d_Flo[(size_t)NT*KT1];
__device__ __align__(16) float d_Y1[(size_t)NT*256];          // layer1 raw acc [n][o]
__device__ __align__(16) float d_qmax[Bq*Sq*256], d_qmin[Bq*Sq*256];
__device__ float d_psY[256*NTILES], d_psQ[256*NTILES];        // transposed partials
__device__ float d_aA[2*256], d_cA[2*256];

// ---------------- helpers ----------------------------------------------------
__device__ __forceinline__ float sqdist(float px, float py, float pz,
                                        float cx, float cy, float cz) {
    float dx = px - cx, dy = py - cy, dz = pz - cz;
    return __fadd_rn(__fadd_rn(__fmul_rn(dx, dx), __fmul_rn(dy, dy)),
                     __fmul_rn(dz, dz));
}

__device__ __forceinline__ void split2(float v, bf16& h, bf16& l) {
    h = __float2bfloat16(v);
    l = __float2bfloat16(v - __bfloat162float(h));
}

__device__ __forceinline__ unsigned long long umax64(unsigned long long a,
                                                     unsigned long long b) {
    return a > b ? a : b;
}

__device__ __forceinline__ void mma16816(float d[4], uint32_t a0, uint32_t a1,
                                         uint32_t a2, uint32_t a3,
                                         uint32_t b0, uint32_t b1) {
    asm volatile(
        "mma.sync.aligned.m16n8k16.row.col.f32.bf16.bf16.f32 "
        "{%0,%1,%2,%3}, {%4,%5,%6,%7}, {%8,%9}, {%0,%1,%2,%3};"
        : "+f"(d[0]), "+f"(d[1]), "+f"(d[2]), "+f"(d[3])
        : "r"(a0), "r"(a1), "r"(a2), "r"(a3), "r"(b0), "r"(b1));
}

#define CP16(dst, src) \
    asm volatile("cp.async.cg.shared.global [%0], [%1], 16;" :: "r"(dst), "l"(src) : "memory")
#define CP_COMMIT() asm volatile("cp.async.commit_group;" ::: "memory")
#define CP_WAIT1()  asm volatile("cp.async.wait_group 1;" ::: "memory")
#define CP_WAIT0()  asm volatile("cp.async.wait_group 0;" ::: "memory")

// ---------------------------- FPS (R9 + tree-max final scan) ------------------
__global__ void __launch_bounds__(512) fps_kernel(const float* __restrict__ xyz,
                                                  float* __restrict__ out) {
    int b = blockIdx.x, t = threadIdx.x;
    const float* base = xyz + (size_t)b * Nq * 3;
    float px[8], py[8], pz[8], dist[8];
#pragma unroll
    for (int i = 0; i < 8; i++) {
        int n = i * 512 + t;
        px[i] = base[n*3+0]; py[i] = base[n*3+1]; pz[i] = base[n*3+2];
        dist[i] = 1e10f;
    }
    __shared__ unsigned long long wred[2][16];
    int lane = t & 31, w = t >> 5;
    int far = 0;
    for (int it = 0; it < Sq; it++) {
        float cx = __ldg(base + far*3 + 0);
        float cy = __ldg(base + far*3 + 1);
        float cz = __ldg(base + far*3 + 2);
        if (t == 0) {
            int o = (b*Sq + it) * 3;
            d_newxyz[o] = cx; d_newxyz[o+1] = cy; d_newxyz[o+2] = cz;
            out[o] = cx; out[o+1] = cy; out[o+2] = cz;
        }
        unsigned long long best = 0ULL;
#pragma unroll
        for (int i = 0; i < 8; i++) {
            float d  = sqdist(px[i], py[i], pz[i], cx, cy, cz);
            float dd = fminf(dist[i], d);
            dist[i]  = dd;
            unsigned long long key =
                ((unsigned long long)__float_as_uint(dd) << 32) |
                (unsigned)~(unsigned)(i*512 + t);
            if (key > best) best = key;
        }
#pragma unroll
        for (int off = 16; off > 0; off >>= 1) {
            unsigned long long o2 = __shfl_down_sync(0xFFFFFFFFu, best, off);
            if (o2 > best) best = o2;
        }
        if (lane == 0) wred[it & 1][w] = best;
        __syncthreads();
        const unsigned long long* wr = wred[it & 1];
        unsigned long long t0 = umax64(wr[0],  wr[1]);
        unsigned long long t1 = umax64(wr[2],  wr[3]);
        unsigned long long t2 = umax64(wr[4],  wr[5]);
        unsigned long long t3 = umax64(wr[6],  wr[7]);
        unsigned long long t4 = umax64(wr[8],  wr[9]);
        unsigned long long t5 = umax64(wr[10], wr[11]);
        unsigned long long t6 = umax64(wr[12], wr[13]);
        unsigned long long t7 = umax64(wr[14], wr[15]);
        unsigned long long s0 = umax64(umax64(t0, t1), umax64(t2, t3));
        unsigned long long s1 = umax64(umax64(t4, t5), umax64(t6, t7));
        far = (int)(~(unsigned)umax64(s0, s1));
    }
}

// ------------------ fused kNN + gather + bf16-split (R9 version) --------------
__global__ void __launch_bounds__(256) knng_kernel(const float* __restrict__ xyz,
                                                   const float* __restrict__ points) {
    int s = blockIdx.x, b = blockIdx.y, t = threadIdx.x;
    const float* base = xyz + (size_t)b * Nq * 3;
    int qo = b*Sq + s;
    float cx = d_newxyz[qo*3], cy = d_newxyz[qo*3+1], cz = d_newxyz[qo*3+2];

    __shared__ float ds[Nq];
    __shared__ unsigned long long wred[8];
    __shared__ unsigned long long winner;
    __shared__ int idx[Kq];

    unsigned long long best = ~0ULL;
#pragma unroll 4
    for (int j = 0; j < 16; j++) {
        int n = j*256 + t;
        float d = sqdist(base[n*3], base[n*3+1], base[n*3+2], cx, cy, cz);
        ds[n] = d;
        unsigned long long key =
            ((unsigned long long)__float_as_uint(d) << 32) | (unsigned)n;
        if (key < best) best = key;
    }
    int lane = t & 31, w = t >> 5;
    for (int r = 0; r < Kq; r++) {
        unsigned long long v = best;
#pragma unroll
        for (int off = 16; off > 0; off >>= 1) {
            unsigned long long o2 = __shfl_down_sync(0xFFFFFFFFu, v, off);
            if (o2 < v) v = o2;
        }
        if (lane == 0) wred[w] = v;
        __syncthreads();
        if (t == 0) {
            unsigned long long m = wred[0];
#pragma unroll
            for (int i = 1; i < 8; i++) if (wred[i] < m) m = wred[i];
            winner = m;
            idx[r] = (int)(unsigned)m;
        }
        __syncthreads();
        if (r < Kq-1) {
            unsigned widx = (unsigned)winner;
            if ((widx & 255u) == (unsigned)t) {
                ds[widx] = CUDART_INF_F;
                best = ~0ULL;
#pragma unroll 4
                for (int j = 0; j < 16; j++) {
                    int n = j*256 + t;
                    unsigned long long key =
                        ((unsigned long long)__float_as_uint(ds[n]) << 32) | (unsigned)n;
                    if (key < best) best = key;
                }
            }
        }
    }
    __syncthreads();
    // gather + split
    const float* pbase = points + (size_t)b * Nq * Dq;
    size_t rowb = (size_t)qo * Kq * KT1;
    for (int e = t; e < Kq*KT1; e += 256) {
        int k = e / KT1, c = e - k*KT1;
        int n = idx[k];
        float v = 0.0f;
        if (c < 3) v = base[n*3 + c] - ((c == 0) ? cx : ((c == 1) ? cy : cz));
        else if (c < CIN) v = pbase[(size_t)n*Dq + (c-3)];
        bf16 h, l; split2(v, h, l);
        d_Fhi[rowb + e] = h; d_Flo[rowb + e] = l;
    }
}

// ------------------- weight split + pad (split into 2 launches) ----------------
__global__ void prep1_kernel(const float* __restrict__ W1) {
    int i = blockIdx.x * 256 + threadIdx.x;
    if (i < 256*KT1) {
        int o = i / KT1, c = i - o*KT1;
        float v = (c < CIN) ? W1[o*CIN + c] : 0.0f;
        bf16 h, l; split2(v, h, l);
        d_W1hi[i] = h; d_W1lo[i] = l;
    }
}

__global__ void prep2_kernel(const float* __restrict__ W2) {
    int i = blockIdx.x * 256 + threadIdx.x;
    if (i < 256*KT2) {
        int o = i >> 8, c = i & 255;
        bf16 h, l; split2(W2[o*256 + c], h, l);
        d_W2hi[i] = h; d_W2lo[i] = l;
    }
}

// ---------- pipelined HMMA split-bf16 GEMM (R9: triple buffer, 1 sync) ---------
#define ST  40
#define APL (128*ST*2)            // 10240 B per A plane
#define WPL (256*ST*2)            // 20480 B per W plane
#define OFF_ALO APL
#define OFF_WHI (2*APL)
#define OFF_WLO (2*APL + WPL)
#define BUFSZ   (2*APL + 2*WPL)   // 61440
#define SM_YS   (3*BUFSZ)
#define SM_QS   (SM_YS + 1024)
#define SM_A1   (SM_QS + 1024)
#define SM_C1   (SM_A1 + 1024)
#define SM_TOT  (SM_C1 + 1024)    // 188416

__device__ __forceinline__ void stageW(char* dst, const bf16* __restrict__ Wh,
                                       const bf16* __restrict__ Wl,
                                       int KT, int kb, int tid) {
#pragma unroll
    for (int it = 0; it < 4; it++) {
        int u = tid + it*256, o = u >> 2, q = u & 3;
        size_t go = (size_t)o*KT + kb*32 + q*8;
        uint32_t sh = (uint32_t)__cvta_generic_to_shared(dst + OFF_WHI + (o*ST + q*8)*2);
        uint32_t sl = (uint32_t)__cvta_generic_to_shared(dst + OFF_WLO + (o*ST + q*8)*2);
        CP16(sh, Wh + go);
        CP16(sl, Wl + go);
    }
}

__device__ __forceinline__ void stageA0(char* dst, int nbase, int kb, int tid) {
#pragma unroll
    for (int it = 0; it < 2; it++) {
        int u = tid + it*256, r = u >> 2, q = u & 3;
        size_t go = (size_t)(nbase + r)*KT1 + kb*32 + q*8;
        uint32_t sh = (uint32_t)__cvta_generic_to_shared(dst + (r*ST + q*8)*2);
        uint32_t sl = (uint32_t)__cvta_generic_to_shared(dst + OFF_ALO + (r*ST + q*8)*2);
        CP16(sh, d_Fhi + go);
        CP16(sl, d_Flo + go);
    }
}

__device__ __forceinline__ void prefA1(float4 rg[4], int nbase, int kb, int tid) {
#pragma unroll
    for (int it = 0; it < 2; it++) {
        int u = tid + it*256, r = u >> 2, q = u & 3;
        const float* src = d_Y1 + (size_t)(nbase + r)*256 + kb*32 + q*8;
        rg[it*2]   = *(const float4*)src;
        rg[it*2+1] = *(const float4*)(src + 4);
    }
}

__device__ __forceinline__ void stageA1(char* dst, const float4 rg[4], int kb,
                                        int tid, const float* sA, const float* sC) {
#pragma unroll
    for (int it = 0; it < 2; it++) {
        int u = tid + it*256, r = u >> 2, q = u & 3;
        int cb = kb*32 + q*8;
        float vs[8] = {rg[it*2].x, rg[it*2].y, rg[it*2].z, rg[it*2].w,
                       rg[it*2+1].x, rg[it*2+1].y, rg[it*2+1].z, rg[it*2+1].w};
        uint32_t hp[4], lp[4];
#pragma unroll
        for (int jp = 0; jp < 4; jp++) {
            float v0 = fmaxf(fmaf(vs[2*jp],   sA[cb+2*jp],   sC[cb+2*jp]),   0.0f);
            float v1 = fmaxf(fmaf(vs[2*jp+1], sA[cb+2*jp+1], sC[cb+2*jp+1]), 0.0f);
            bf16 h0, l0, h1, l1;
            split2(v0, h0, l0); split2(v1, h1, l1);
            hp[jp] = (uint32_t)__bfloat16_as_ushort(h0) |
                     ((uint32_t)__bfloat16_as_ushort(h1) << 16);
            lp[jp] = (uint32_t)__bfloat16_as_ushort(l0) |
                     ((uint32_t)__bfloat16_as_ushort(l1) << 16);
        }
        *(uint4*)(dst + (r*ST + q*8)*2)           = make_uint4(hp[0], hp[1], hp[2], hp[3]);
        *(uint4*)(dst + OFF_ALO + (r*ST + q*8)*2) = make_uint4(lp[0], lp[1], lp[2], lp[3]);
    }
}

__device__ __forceinline__ void compute_chunk(const char* smc, int wn, int wo,
                                              int g, int m, float acc[4][8][4]) {
#pragma unroll
    for (int ks = 0; ks < 2; ks++) {
        int cb = ks*16 + 2*m;
        uint32_t ah[4][4], al[4][4];
#pragma unroll
        for (int i = 0; i < 4; i++) {
            int r0 = wn*64 + i*16 + g;
            ah[i][0] = *(const uint32_t*)(smc + (r0*ST + cb)*2);
            ah[i][1] = *(const uint32_t*)(smc + ((r0+8)*ST + cb)*2);
            ah[i][2] = *(const uint32_t*)(smc + (r0*ST + cb + 8)*2);
            ah[i][3] = *(const uint32_t*)(smc + ((r0+8)*ST + cb + 8)*2);
            al[i][0] = *(const uint32_t*)(smc + OFF_ALO + (r0*ST + cb)*2);
            al[i][1] = *(const uint32_t*)(smc + OFF_ALO + ((r0+8)*ST + cb)*2);
            al[i][2] = *(const uint32_t*)(smc + OFF_ALO + (r0*ST + cb + 8)*2);
            al[i][3] = *(const uint32_t*)(smc + OFF_ALO + ((r0+8)*ST + cb + 8)*2);
        }
#pragma unroll
        for (int j = 0; j < 8; j++) {
            int ro = wo*64 + j*8 + g;
            uint32_t bh0 = *(const uint32_t*)(smc + OFF_WHI + (ro*ST + cb)*2);
            uint32_t bh1 = *(const uint32_t*)(smc + OFF_WHI + (ro*ST + cb + 8)*2);
            uint32_t bl0 = *(const uint32_t*)(smc + OFF_WLO + (ro*ST + cb)*2);
            uint32_t bl1 = *(const uint32_t*)(smc + OFF_WLO + (ro*ST + cb + 8)*2);
#pragma unroll
            for (int i = 0; i < 4; i++) {
                mma16816(acc[i][j], ah[i][0], ah[i][1], ah[i][2], ah[i][3], bh0, bh1);
                mma16816(acc[i][j], al[i][0], al[i][1], al[i][2], al[i][3], bh0, bh1);
                mma16816(acc[i][j], ah[i][0], ah[i][1], ah[i][2], ah[i][3], bl0, bl1);
            }
        }
    }
}

template<int LAYER>
__global__ void __launch_bounds__(256, 1) gemm_kernel() {
    const bf16* Wh = LAYER ? d_W2hi : d_W1hi;
    const bf16* Wl = LAYER ? d_W2lo : d_W1lo;
    const int KT  = LAYER ? KT2 : KT1;
    const int nKB = KT >> 5;

    extern __shared__ char sm[];
    int tid = threadIdx.x, lane = tid & 31, wid = tid >> 5;
    int g = lane >> 2, m = lane & 3;
    int wn = wid & 1, wo = wid >> 1;
    int nbase = blockIdx.x * 128;

    float* sA = (float*)(sm + SM_A1);
    float* sC = (float*)(sm + SM_C1);
    if (LAYER) { sA[tid] = d_aA[tid]; sC[tid] = d_cA[tid]; }

    float acc[4][8][4];
#pragma unroll
    for (int i = 0; i < 4; i++)
#pragma unroll
        for (int j = 0; j < 8; j++)
#pragma unroll
            for (int e = 0; e < 4; e++) acc[i][j][e] = 0.0f;

    float4 rg[4];
    // prologue: stage chunk 0 into buffer 0
    if (LAYER) {
        __syncthreads();            // sA/sC visible
        prefA1(rg, nbase, 0, tid);
        stageA1(sm, rg, 0, tid, sA, sC);
    } else {
        stageA0(sm, nbase, 0, tid);
    }
    stageW(sm, Wh, Wl, KT, 0, tid);
    CP_COMMIT();
    if (LAYER) prefA1(rg, nbase, 1, tid);

    // triple-buffered mainloop: ONE __syncthreads per chunk
    for (int kb = 0; kb < nKB; kb++) {
        char* cur = sm + (kb % 3) * BUFSZ;
        char* nxt = sm + ((kb + 1) % 3) * BUFSZ;
        if (kb + 1 < nKB) {
            if (LAYER) {
                stageA1(nxt, rg, kb + 1, tid, sA, sC);
                if (kb + 2 < nKB) prefA1(rg, nbase, kb + 2, tid);
            } else {
                stageA0(nxt, nbase, kb + 1, tid);
            }
            stageW(nxt, Wh, Wl, KT, kb + 1, tid);
            CP_COMMIT();
            CP_WAIT1();
        } else {
            CP_WAIT0();
        }
        __syncthreads();
        compute_chunk(cur, wn, wo, g, m, acc);
    }
    __syncthreads();

    // ---------------- epilogue -------------------------------------------------
    float* ys = (float*)(sm + SM_YS);
    float* qs = (float*)(sm + SM_QS);
    ys[tid] = 0.0f; qs[tid] = 0.0f;
    __syncthreads();

    float sc[8][2], qc[8][2];
#pragma unroll
    for (int j = 0; j < 8; j++) { sc[j][0]=sc[j][1]=qc[j][0]=qc[j][1]=0.0f; }

#pragma unroll
    for (int i = 0; i < 4; i++) {
        int r0 = nbase + wn*64 + i*16 + g;
#pragma unroll
        for (int j = 0; j < 8; j++) {
            int col = wo*64 + j*8 + 2*m;
            float v0 = acc[i][j][0], v1 = acc[i][j][1];
            float v2 = acc[i][j][2], v3 = acc[i][j][3];
            if (!LAYER) {
                *(float2*)(d_Y1 + (size_t)r0*256 + col)     = make_float2(v0, v1);
                *(float2*)(d_Y1 + (size_t)(r0+8)*256 + col) = make_float2(v2, v3);
            } else {
                // per-query max/min over k (query = 16 consecutive tokens)
                float mxa = fmaxf(v0, v2), mxb = fmaxf(v1, v3);
                float mna = fminf(v0, v2), mnb = fminf(v1, v3);
#pragma unroll
                for (int off = 4; off < 32; off <<= 1) {
                    mxa = fmaxf(mxa, __shfl_xor_sync(0xFFFFFFFFu, mxa, off));
                    mxb = fmaxf(mxb, __shfl_xor_sync(0xFFFFFFFFu, mxb, off));
                    mna = fminf(mna, __shfl_xor_sync(0xFFFFFFFFu, mna, off));
                    mnb = fminf(mnb, __shfl_xor_sync(0xFFFFFFFFu, mnb, off));
                }
                if (g == 0) {
                    int q = blockIdx.x*8 + wn*4 + i;
                    *(float2*)(d_qmax + (size_t)q*256 + col) = make_float2(mxa, mxb);
                    *(float2*)(d_qmin + (size_t)q*256 + col) = make_float2(mna, mnb);
                }
            }
            sc[j][0] += v0 + v2;       sc[j][1] += v1 + v3;
            qc[j][0] += v0*v0 + v2*v2; qc[j][1] += v1*v1 + v3*v3;
        }
    }
#pragma unroll
    for (int j = 0; j < 8; j++)
#pragma unroll
        for (int e = 0; e < 2; e++) {
#pragma unroll
            for (int off = 4; off < 32; off <<= 1) {
                sc[j][e] += __shfl_xor_sync(0xFFFFFFFFu, sc[j][e], off);
                qc[j][e] += __shfl_xor_sync(0xFFFFFFFFu, qc[j][e], off);
            }
        }
    if (wn == 0 && lane < 4) {
#pragma unroll
        for (int j = 0; j < 8; j++) {
            int col = wo*64 + j*8 + 2*lane;
            ys[col] = sc[j][0];   ys[col+1] = sc[j][1];
            qs[col] = qc[j][0];   qs[col+1] = qc[j][1];
        }
    }
    __syncthreads();
    if (wn == 1 && lane < 4) {
#pragma unroll
        for (int j = 0; j < 8; j++) {
            int col = wo*64 + j*8 + 2*lane;
            ys[col] += sc[j][0];  ys[col+1] += sc[j][1];
            qs[col] += qc[j][0];  qs[col+1] += qc[j][1];
        }
    }
    __syncthreads();
    d_psY[(size_t)tid*NTILES + blockIdx.x] = ys[tid];
    d_psQ[(size_t)tid*NTILES + blockIdx.x] = qs[tid];
}

// ---------------- BN stats finalize (256 blocks, coalesced) --------------------
__global__ void __launch_bounds__(256) stats_final(int layer,
                                                   const float* __restrict__ g,
                                                   const float* __restrict__ bt) {
    int o = blockIdx.x, t = threadIdx.x;
    float s = 0.0f, q = 0.0f;
    for (int i = t; i < NTILES; i += 256) {
        s += d_psY[(size_t)o*NTILES + i];
        q += d_psQ[(size_t)o*NTILES + i];
    }
    __shared__ float ss[8], sq[8];
#pragma unroll
    for (int off = 16; off > 0; off >>= 1) {
        s += __shfl_down_sync(0xFFFFFFFFu, s, off);
        q += __shfl_down_sync(0xFFFFFFFFu, q, off);
    }
    if ((t & 31) == 0) { ss[t >> 5] = s; sq[t >> 5] = q; }
    __syncthreads();
    if (t == 0) {
        float S = 0.0f, Q = 0.0f;
#pragma unroll
        for (int i = 0; i < 8; i++) { S += ss[i]; Q += sq[i]; }
        float mean = S * (1.0f / NT);
        float var  = Q * (1.0f / NT) - mean*mean;
        float av = rsqrtf(var + 1e-5f) * g[o];
        d_aA[layer*256 + o] = av;
        d_cA[layer*256 + o] = bt[o] - mean * av;   // bias-free (cancels in BN)
    }
}

// ----------- final: pick max/min by sign(a2), affine + relu --------------------
__global__ void __launch_bounds__(256) final_kernel(float* __restrict__ out) {
    size_t idx = (size_t)blockIdx.x * 256 + threadIdx.x;
    int o = threadIdx.x;
    float a = d_aA[256 + o], c = d_cA[256 + o];
    float v = (a >= 0.0f) ? d_qmax[idx] : d_qmin[idx];
    out[OUT_XYZ + idx] = fmaxf(fmaf(v, a, c), 0.0f);
}

// ------------------------------- launch ----------------------------------------
extern "C" void kernel_launch(void* const* d_in, const int* in_sizes, int n_in,
                              void* d_out, int out_size) {
    const float* xyz    = (const float*)d_in[0];
    const float* points = (const float*)d_in[1];
    const float* W1  = (const float*)d_in[2];
    const float* g1  = (const float*)d_in[4];
    const float* bt1 = (const float*)d_in[5];
    const float* W2  = (const float*)d_in[6];
    const float* g2  = (const float*)d_in[8];
    const float* bt2 = (const float*)d_in[9];
    float* out = (float*)d_out;

    cudaFuncSetAttribute(gemm_kernel<0>, cudaFuncAttributeMaxDynamicSharedMemorySize, SM_TOT);
    cudaFuncSetAttribute(gemm_kernel<1>, cudaFuncAttributeMaxDynamicSharedMemorySize, SM_TOT);

    // launch order chosen so the 4th launch (ncu -s 5 -c 1 capture point)
    // is knng_kernel — the largest still-unprofiled kernel.
    prep1_kernel<<<192, 256>>>(W1);
    prep2_kernel<<<256, 256>>>(W2);
    fps_kernel<<<Bq, 512>>>(xyz, out);
    knng_kernel<<<dim3(Sq, Bq), 256>>>(xyz, points);
    gemm_kernel<0><<<NTILES, 256, SM_TOT>>>();
    stats_final<<<256, 256>>>(0, g1, bt1);
    gemm_kernel<1><<<NTILES, 256, SM_TOT>>>();
    stats_final<<<256, 256>>>(1, g2, bt2);
    final_kernel<<<Bq*Sq, 256>>>(out);
}

// round 11
// speedup vs baseline: 1.0498x; 1.0498x over previous
#include <cuda_runtime.h>
#include <cuda_bf16.h>
#include <math_constants.h>
#include <cstdint>

// Problem constants
#define Bq   16
#define Nq   4096
#define Dq   128
#define Sq   1024
#define Kq   16
#define CIN  131            // 3 + D
#define KT1  192            // layer-1 K padded (6 chunks of 32)
#define KT2  256            // layer-2 K (8 chunks of 32)
#define NT   (Bq*Sq*Kq)     // 262144 tokens
#define NTILES (NT/128)     // 2048 n-tiles
#define OUT_XYZ (Bq*Sq*3)

typedef __nv_bfloat16 bf16;

// ---------------- static device scratch -------------------------------------
__device__ float d_newxyz[Bq*Sq*3];
__device__ __align__(16) bf16 d_W1hi[256*KT1], d_W1lo[256*KT1];
__device__ __align__(16) bf16 d_W2hi[256*KT2], d_W2lo[256*KT2];
__device__ __align__(16) bf16 d_Fhi[(size_t)NT*KT1], d_Flo[(size_t)NT*KT1];
__device__ __align__(16) float d_Y1[(size_t)NT*256];          // layer1 raw acc [n][o]
__device__ __align__(16) float d_qmax[Bq*Sq*256], d_qmin[Bq*Sq*256];
__device__ float d_psY[256*NTILES], d_psQ[256*NTILES];        // transposed partials
__device__ float d_aA[2*256], d_cA[2*256];

// ---------------- helpers ----------------------------------------------------
__device__ __forceinline__ float sqdist(float px, float py, float pz,
                                        float cx, float cy, float cz) {
    float dx = px - cx, dy = py - cy, dz = pz - cz;
    return __fadd_rn(__fadd_rn(__fmul_rn(dx, dx), __fmul_rn(dy, dy)),
                     __fmul_rn(dz, dz));
}

__device__ __forceinline__ void split2(float v, bf16& h, bf16& l) {
    h = __float2bfloat16(v);
    l = __float2bfloat16(v - __bfloat162float(h));
}

__device__ __forceinline__ unsigned long long umax64(unsigned long long a,
                                                     unsigned long long b) {
    return a > b ? a : b;
}

__device__ __forceinline__ void mma16816(float d[4], uint32_t a0, uint32_t a1,
                                         uint32_t a2, uint32_t a3,
                                         uint32_t b0, uint32_t b1) {
    asm volatile(
        "mma.sync.aligned.m16n8k16.row.col.f32.bf16.bf16.f32 "
        "{%0,%1,%2,%3}, {%4,%5,%6,%7}, {%8,%9}, {%0,%1,%2,%3};"
        : "+f"(d[0]), "+f"(d[1]), "+f"(d[2]), "+f"(d[3])
        : "r"(a0), "r"(a1), "r"(a2), "r"(a3), "r"(b0), "r"(b1));
}

#define CP16(dst, src) \
    asm volatile("cp.async.cg.shared.global [%0], [%1], 16;" :: "r"(dst), "l"(src) : "memory")
#define CP_COMMIT() asm volatile("cp.async.commit_group;" ::: "memory")
#define CP_WAIT1()  asm volatile("cp.async.wait_group 1;" ::: "memory")
#define CP_WAIT0()  asm volatile("cp.async.wait_group 0;" ::: "memory")

// ---------------------------- FPS (R10 version) --------------------------------
__global__ void __launch_bounds__(512) fps_kernel(const float* __restrict__ xyz,
                                                  float* __restrict__ out) {
    int b = blockIdx.x, t = threadIdx.x;
    const float* base = xyz + (size_t)b * Nq * 3;
    float px[8], py[8], pz[8], dist[8];
#pragma unroll
    for (int i = 0; i < 8; i++) {
        int n = i * 512 + t;
        px[i] = base[n*3+0]; py[i] = base[n*3+1]; pz[i] = base[n*3+2];
        dist[i] = 1e10f;
    }
    __shared__ unsigned long long wred[2][16];
    int lane = t & 31, w = t >> 5;
    int far = 0;
    for (int it = 0; it < Sq; it++) {
        float cx = __ldg(base + far*3 + 0);
        float cy = __ldg(base + far*3 + 1);
        float cz = __ldg(base + far*3 + 2);
        if (t == 0) {
            int o = (b*Sq + it) * 3;
            d_newxyz[o] = cx; d_newxyz[o+1] = cy; d_newxyz[o+2] = cz;
            out[o] = cx; out[o+1] = cy; out[o+2] = cz;
        }
        unsigned long long best = 0ULL;
#pragma unroll
        for (int i = 0; i < 8; i++) {
            float d  = sqdist(px[i], py[i], pz[i], cx, cy, cz);
            float dd = fminf(dist[i], d);
            dist[i]  = dd;
            unsigned long long key =
                ((unsigned long long)__float_as_uint(dd) << 32) |
                (unsigned)~(unsigned)(i*512 + t);
            if (key > best) best = key;
        }
#pragma unroll
        for (int off = 16; off > 0; off >>= 1) {
            unsigned long long o2 = __shfl_down_sync(0xFFFFFFFFu, best, off);
            if (o2 > best) best = o2;
        }
        if (lane == 0) wred[it & 1][w] = best;
        __syncthreads();
        const unsigned long long* wr = wred[it & 1];
        unsigned long long t0 = umax64(wr[0],  wr[1]);
        unsigned long long t1 = umax64(wr[2],  wr[3]);
        unsigned long long t2 = umax64(wr[4],  wr[5]);
        unsigned long long t3 = umax64(wr[6],  wr[7]);
        unsigned long long t4 = umax64(wr[8],  wr[9]);
        unsigned long long t5 = umax64(wr[10], wr[11]);
        unsigned long long t6 = umax64(wr[12], wr[13]);
        unsigned long long t7 = umax64(wr[14], wr[15]);
        unsigned long long s0 = umax64(umax64(t0, t1), umax64(t2, t3));
        unsigned long long s1 = umax64(umax64(t4, t5), umax64(t6, t7));
        far = (int)(~(unsigned)umax64(s0, s1));
    }
}

// -------- fused kNN + gather + bf16-split (redux.min selection rounds) ---------
__global__ void __launch_bounds__(256) knng_kernel(const float* __restrict__ xyz,
                                                   const float* __restrict__ points) {
    int s = blockIdx.x, b = blockIdx.y, t = threadIdx.x;
    const float* base = xyz + (size_t)b * Nq * 3;
    int qo = b*Sq + s;
    float cx = d_newxyz[qo*3], cy = d_newxyz[qo*3+1], cz = d_newxyz[qo*3+2];

    __shared__ float ds[Nq];
    __shared__ unsigned long long wred[8];
    __shared__ unsigned long long winner;
    __shared__ int idx[Kq];

    // pass 1: distances + per-thread running lexicographic min (d, n)
    unsigned bd = 0xFFFFFFFFu, bi = 0u;
#pragma unroll 4
    for (int j = 0; j < 16; j++) {
        int n = j*256 + t;
        float d = sqdist(base[n*3], base[n*3+1], base[n*3+2], cx, cy, cz);
        ds[n] = d;
        unsigned ud = __float_as_uint(d);
        if (ud < bd) { bd = ud; bi = (unsigned)n; }   // ties keep earlier n
    }
    int lane = t & 31, w = t >> 5;
    for (int r = 0; r < Kq; r++) {
        // warp lexicographic min via two u32 redux ops
        unsigned wd = __reduce_min_sync(0xFFFFFFFFu, bd);
        unsigned ci = (bd == wd) ? bi : 0xFFFFFFFFu;
        unsigned wi = __reduce_min_sync(0xFFFFFFFFu, ci);
        if (lane == 0) wred[w] = ((unsigned long long)wd << 32) | wi;
        __syncthreads();
        if (t == 0) {
            unsigned long long m = wred[0];
#pragma unroll
            for (int i = 1; i < 8; i++) if (wred[i] < m) m = wred[i];
            winner = m;
            idx[r] = (int)(unsigned)m;
        }
        __syncthreads();
        if (r < Kq-1) {
            unsigned widx = (unsigned)winner;
            if ((widx & 255u) == (unsigned)t) {
                ds[widx] = CUDART_INF_F;
                bd = 0xFFFFFFFFu; bi = 0u;
#pragma unroll 4
                for (int j = 0; j < 16; j++) {
                    int n = j*256 + t;
                    unsigned ud = __float_as_uint(ds[n]);
                    if (ud < bd) { bd = ud; bi = (unsigned)n; }
                }
            }
        }
    }
    __syncthreads();
    // gather + split
    const float* pbase = points + (size_t)b * Nq * Dq;
    size_t rowb = (size_t)qo * Kq * KT1;
    for (int e = t; e < Kq*KT1; e += 256) {
        int k = e / KT1, c = e - k*KT1;
        int n = idx[k];
        float v = 0.0f;
        if (c < 3) v = base[n*3 + c] - ((c == 0) ? cx : ((c == 1) ? cy : cz));
        else if (c < CIN) v = pbase[(size_t)n*Dq + (c-3)];
        bf16 h, l; split2(v, h, l);
        d_Fhi[rowb + e] = h; d_Flo[rowb + e] = l;
    }
}

// ------------------- weight split + pad (split into 2 launches) ----------------
__global__ void prep1_kernel(const float* __restrict__ W1) {
    int i = blockIdx.x * 256 + threadIdx.x;
    if (i < 256*KT1) {
        int o = i / KT1, c = i - o*KT1;
        float v = (c < CIN) ? W1[o*CIN + c] : 0.0f;
        bf16 h, l; split2(v, h, l);
        d_W1hi[i] = h; d_W1lo[i] = l;
    }
}

__global__ void prep2_kernel(const float* __restrict__ W2) {
    int i = blockIdx.x * 256 + threadIdx.x;
    if (i < 256*KT2) {
        int o = i >> 8, c = i & 255;
        bf16 h, l; split2(W2[o*256 + c], h, l);
        d_W2hi[i] = h; d_W2lo[i] = l;
    }
}

// ---------- pipelined HMMA split-bf16 GEMM (R9: triple buffer, 1 sync) ---------
#define ST  40
#define APL (128*ST*2)            // 10240 B per A plane
#define WPL (256*ST*2)            // 20480 B per W plane
#define OFF_ALO APL
#define OFF_WHI (2*APL)
#define OFF_WLO (2*APL + WPL)
#define BUFSZ   (2*APL + 2*WPL)   // 61440
#define SM_YS   (3*BUFSZ)
#define SM_QS   (SM_YS + 1024)
#define SM_A1   (SM_QS + 1024)
#define SM_C1   (SM_A1 + 1024)
#define SM_TOT  (SM_C1 + 1024)    // 188416

__device__ __forceinline__ void stageW(char* dst, const bf16* __restrict__ Wh,
                                       const bf16* __restrict__ Wl,
                                       int KT, int kb, int tid) {
#pragma unroll
    for (int it = 0; it < 4; it++) {
        int u = tid + it*256, o = u >> 2, q = u & 3;
        size_t go = (size_t)o*KT + kb*32 + q*8;
        uint32_t sh = (uint32_t)__cvta_generic_to_shared(dst + OFF_WHI + (o*ST + q*8)*2);
        uint32_t sl = (uint32_t)__cvta_generic_to_shared(dst + OFF_WLO + (o*ST + q*8)*2);
        CP16(sh, Wh + go);
        CP16(sl, Wl + go);
    }
}

__device__ __forceinline__ void stageA0(char* dst, int nbase, int kb, int tid) {
#pragma unroll
    for (int it = 0; it < 2; it++) {
        int u = tid + it*256, r = u >> 2, q = u & 3;
        size_t go = (size_t)(nbase + r)*KT1 + kb*32 + q*8;
        uint32_t sh = (uint32_t)__cvta_generic_to_shared(dst + (r*ST + q*8)*2);
        uint32_t sl = (uint32_t)__cvta_generic_to_shared(dst + OFF_ALO + (r*ST + q*8)*2);
        CP16(sh, d_Fhi + go);
        CP16(sl, d_Flo + go);
    }
}

__device__ __forceinline__ void prefA1(float4 rg[4], int nbase, int kb, int tid) {
#pragma unroll
    for (int it = 0; it < 2; it++) {
        int u = tid + it*256, r = u >> 2, q = u & 3;
        const float* src = d_Y1 + (size_t)(nbase + r)*256 + kb*32 + q*8;
        rg[it*2]   = *(const float4*)src;
        rg[it*2+1] = *(const float4*)(src + 4);
    }
}

__device__ __forceinline__ void stageA1(char* dst, const float4 rg[4], int kb,
                                        int tid, const float* sA, const float* sC) {
#pragma unroll
    for (int it = 0; it < 2; it++) {
        int u = tid + it*256, r = u >> 2, q = u & 3;
        int cb = kb*32 + q*8;
        float vs[8] = {rg[it*2].x, rg[it*2].y, rg[it*2].z, rg[it*2].w,
                       rg[it*2+1].x, rg[it*2+1].y, rg[it*2+1].z, rg[it*2+1].w};
        uint32_t hp[4], lp[4];
#pragma unroll
        for (int jp = 0; jp < 4; jp++) {
            float v0 = fmaxf(fmaf(vs[2*jp],   sA[cb+2*jp],   sC[cb+2*jp]),   0.0f);
            float v1 = fmaxf(fmaf(vs[2*jp+1], sA[cb+2*jp+1], sC[cb+2*jp+1]), 0.0f);
            bf16 h0, l0, h1, l1;
            split2(v0, h0, l0); split2(v1, h1, l1);
            hp[jp] = (uint32_t)__bfloat16_as_ushort(h0) |
                     ((uint32_t)__bfloat16_as_ushort(h1) << 16);
            lp[jp] = (uint32_t)__bfloat16_as_ushort(l0) |
                     ((uint32_t)__bfloat16_as_ushort(l1) << 16);
        }
        *(uint4*)(dst + (r*ST + q*8)*2)           = make_uint4(hp[0], hp[1], hp[2], hp[3]);
        *(uint4*)(dst + OFF_ALO + (r*ST + q*8)*2) = make_uint4(lp[0], lp[1], lp[2], lp[3]);
    }
}

__device__ __forceinline__ void compute_chunk(const char* smc, int wn, int wo,
                                              int g, int m, float acc[4][8][4]) {
#pragma unroll
    for (int ks = 0; ks < 2; ks++) {
        int cb = ks*16 + 2*m;
        uint32_t ah[4][4], al[4][4];
#pragma unroll
        for (int i = 0; i < 4; i++) {
            int r0 = wn*64 + i*16 + g;
            ah[i][0] = *(const uint32_t*)(smc + (r0*ST + cb)*2);
            ah[i][1] = *(const uint32_t*)(smc + ((r0+8)*ST + cb)*2);
            ah[i][2] = *(const uint32_t*)(smc + (r0*ST + cb + 8)*2);
            ah[i][3] = *(const uint32_t*)(smc + ((r0+8)*ST + cb + 8)*2);
            al[i][0] = *(const uint32_t*)(smc + OFF_ALO + (r0*ST + cb)*2);
            al[i][1] = *(const uint32_t*)(smc + OFF_ALO + ((r0+8)*ST + cb)*2);
            al[i][2] = *(const uint32_t*)(smc + OFF_ALO + (r0*ST + cb + 8)*2);
            al[i][3] = *(const uint32_t*)(smc + OFF_ALO + ((r0+8)*ST + cb + 8)*2);
        }
#pragma unroll
        for (int j = 0; j < 8; j++) {
            int ro = wo*64 + j*8 + g;
            uint32_t bh0 = *(const uint32_t*)(smc + OFF_WHI + (ro*ST + cb)*2);
            uint32_t bh1 = *(const uint32_t*)(smc + OFF_WHI + (ro*ST + cb + 8)*2);
            uint32_t bl0 = *(const uint32_t*)(smc + OFF_WLO + (ro*ST + cb)*2);
            uint32_t bl1 = *(const uint32_t*)(smc + OFF_WLO + (ro*ST + cb + 8)*2);
#pragma unroll
            for (int i = 0; i < 4; i++) {
                mma16816(acc[i][j], ah[i][0], ah[i][1], ah[i][2], ah[i][3], bh0, bh1);
                mma16816(acc[i][j], al[i][0], al[i][1], al[i][2], al[i][3], bh0, bh1);
                mma16816(acc[i][j], ah[i][0], ah[i][1], ah[i][2], ah[i][3], bl0, bl1);
            }
        }
    }
}

template<int LAYER>
__global__ void __launch_bounds__(256, 1) gemm_kernel() {
    const bf16* Wh = LAYER ? d_W2hi : d_W1hi;
    const bf16* Wl = LAYER ? d_W2lo : d_W1lo;
    const int KT  = LAYER ? KT2 : KT1;
    const int nKB = KT >> 5;

    extern __shared__ char sm[];
    int tid = threadIdx.x, lane = tid & 31, wid = tid >> 5;
    int g = lane >> 2, m = lane & 3;
    int wn = wid & 1, wo = wid >> 1;
    int nbase = blockIdx.x * 128;

    float* sA = (float*)(sm + SM_A1);
    float* sC = (float*)(sm + SM_C1);
    if (LAYER) { sA[tid] = d_aA[tid]; sC[tid] = d_cA[tid]; }

    float acc[4][8][4];
#pragma unroll
    for (int i = 0; i < 4; i++)
#pragma unroll
        for (int j = 0; j < 8; j++)
#pragma unroll
            for (int e = 0; e < 4; e++) acc[i][j][e] = 0.0f;

    float4 rg[4];
    // prologue: stage chunk 0 into buffer 0
    if (LAYER) {
        __syncthreads();            // sA/sC visible
        prefA1(rg, nbase, 0, tid);
        stageA1(sm, rg, 0, tid, sA, sC);
    } else {
        stageA0(sm, nbase, 0, tid);
    }
    stageW(sm, Wh, Wl, KT, 0, tid);
    CP_COMMIT();
    if (LAYER) prefA1(rg, nbase, 1, tid);

    // triple-buffered mainloop: ONE __syncthreads per chunk
    for (int kb = 0; kb < nKB; kb++) {
        char* cur = sm + (kb % 3) * BUFSZ;
        char* nxt = sm + ((kb + 1) % 3) * BUFSZ;
        if (kb + 1 < nKB) {
            if (LAYER) {
                stageA1(nxt, rg, kb + 1, tid, sA, sC);
                if (kb + 2 < nKB) prefA1(rg, nbase, kb + 2, tid);
            } else {
                stageA0(nxt, nbase, kb + 1, tid);
            }
            stageW(nxt, Wh, Wl, KT, kb + 1, tid);
            CP_COMMIT();
            CP_WAIT1();
        } else {
            CP_WAIT0();
        }
        __syncthreads();
        compute_chunk(cur, wn, wo, g, m, acc);
    }
    __syncthreads();

    // ---------------- epilogue -------------------------------------------------
    float* ys = (float*)(sm + SM_YS);
    float* qs = (float*)(sm + SM_QS);
    ys[tid] = 0.0f; qs[tid] = 0.0f;
    __syncthreads();

    float sc[8][2], qc[8][2];
#pragma unroll
    for (int j = 0; j < 8; j++) { sc[j][0]=sc[j][1]=qc[j][0]=qc[j][1]=0.0f; }

#pragma unroll
    for (int i = 0; i < 4; i++) {
        int r0 = nbase + wn*64 + i*16 + g;
#pragma unroll
        for (int j = 0; j < 8; j++) {
            int col = wo*64 + j*8 + 2*m;
            float v0 = acc[i][j][0], v1 = acc[i][j][1];
            float v2 = acc[i][j][2], v3 = acc[i][j][3];
            if (!LAYER) {
                *(float2*)(d_Y1 + (size_t)r0*256 + col)     = make_float2(v0, v1);
                *(float2*)(d_Y1 + (size_t)(r0+8)*256 + col) = make_float2(v2, v3);
            } else {
                // per-query max/min over k (query = 16 consecutive tokens)
                float mxa = fmaxf(v0, v2), mxb = fmaxf(v1, v3);
                float mna = fminf(v0, v2), mnb = fminf(v1, v3);
#pragma unroll
                for (int off = 4; off < 32; off <<= 1) {
                    mxa = fmaxf(mxa, __shfl_xor_sync(0xFFFFFFFFu, mxa, off));
                    mxb = fmaxf(mxb, __shfl_xor_sync(0xFFFFFFFFu, mxb, off));
                    mna = fminf(mna, __shfl_xor_sync(0xFFFFFFFFu, mna, off));
                    mnb = fminf(mnb, __shfl_xor_sync(0xFFFFFFFFu, mnb, off));
                }
                if (g == 0) {
                    int q = blockIdx.x*8 + wn*4 + i;
                    *(float2*)(d_qmax + (size_t)q*256 + col) = make_float2(mxa, mxb);
                    *(float2*)(d_qmin + (size_t)q*256 + col) = make_float2(mna, mnb);
                }
            }
            sc[j][0] += v0 + v2;       sc[j][1] += v1 + v3;
            qc[j][0] += v0*v0 + v2*v2; qc[j][1] += v1*v1 + v3*v3;
        }
    }
#pragma unroll
    for (int j = 0; j < 8; j++)
#pragma unroll
        for (int e = 0; e < 2; e++) {
#pragma unroll
            for (int off = 4; off < 32; off <<= 1) {
                sc[j][e] += __shfl_xor_sync(0xFFFFFFFFu, sc[j][e], off);
                qc[j][e] += __shfl_xor_sync(0xFFFFFFFFu, qc[j][e], off);
            }
        }
    if (wn == 0 && lane < 4) {
#pragma unroll
        for (int j = 0; j < 8; j++) {
            int col = wo*64 + j*8 + 2*lane;
            ys[col] = sc[j][0];   ys[col+1] = sc[j][1];
            qs[col] = qc[j][0];   qs[col+1] = qc[j][1];
        }
    }
    __syncthreads();
    if (wn == 1 && lane < 4) {
#pragma unroll
        for (int j = 0; j < 8; j++) {
            int col = wo*64 + j*8 + 2*lane;
            ys[col] += sc[j][0];  ys[col+1] += sc[j][1];
            qs[col] += qc[j][0];  qs[col+1] += qc[j][1];
        }
    }
    __syncthreads();
    d_psY[(size_t)tid*NTILES + blockIdx.x] = ys[tid];
    d_psQ[(size_t)tid*NTILES + blockIdx.x] = qs[tid];
}

// ---------------- BN stats finalize (256 blocks, coalesced) --------------------
__global__ void __launch_bounds__(256) stats_final(int layer,
                                                   const float* __restrict__ g,
                                                   const float* __restrict__ bt) {
    int o = blockIdx.x, t = threadIdx.x;
    float s = 0.0f, q = 0.0f;
    for (int i = t; i < NTILES; i += 256) {
        s += d_psY[(size_t)o*NTILES + i];
        q += d_psQ[(size_t)o*NTILES + i];
    }
    __shared__ float ss[8], sq[8];
#pragma unroll
    for (int off = 16; off > 0; off >>= 1) {
        s += __shfl_down_sync(0xFFFFFFFFu, s, off);
        q += __shfl_down_sync(0xFFFFFFFFu, q, off);
    }
    if ((t & 31) == 0) { ss[t >> 5] = s; sq[t >> 5] = q; }
    __syncthreads();
    if (t == 0) {
        float S = 0.0f, Q = 0.0f;
#pragma unroll
        for (int i = 0; i < 8; i++) { S += ss[i]; Q += sq[i]; }
        float mean = S * (1.0f / NT);
        float var  = Q * (1.0f / NT) - mean*mean;
        float av = rsqrtf(var + 1e-5f) * g[o];
        d_aA[layer*256 + o] = av;
        d_cA[layer*256 + o] = bt[o] - mean * av;   // bias-free (cancels in BN)
    }
}

// ----------- final: pick max/min by sign(a2), affine + relu --------------------
__global__ void __launch_bounds__(256) final_kernel(float* __restrict__ out) {
    size_t idx = (size_t)blockIdx.x * 256 + threadIdx.x;
    int o = threadIdx.x;
    float a = d_aA[256 + o], c = d_cA[256 + o];
    float v = (a >= 0.0f) ? d_qmax[idx] : d_qmin[idx];
    out[OUT_XYZ + idx] = fmaxf(fmaf(v, a, c), 0.0f);
}

// ------------------------------- launch ----------------------------------------
extern "C" void kernel_launch(void* const* d_in, const int* in_sizes, int n_in,
                              void* d_out, int out_size) {
    const float* xyz    = (const float*)d_in[0];
    const float* points = (const float*)d_in[1];
    const float* W1  = (const float*)d_in[2];
    const float* g1  = (const float*)d_in[4];
    const float* bt1 = (const float*)d_in[5];
    const float* W2  = (const float*)d_in[6];
    const float* g2  = (const float*)d_in[8];
    const float* bt2 = (const float*)d_in[9];
    float* out = (float*)d_out;

    cudaFuncSetAttribute(gemm_kernel<0>, cudaFuncAttributeMaxDynamicSharedMemorySize, SM_TOT);
    cudaFuncSetAttribute(gemm_kernel<1>, cudaFuncAttributeMaxDynamicSharedMemorySize, SM_TOT);

    // keep knng as the 4th launch so ncu captures it (verify the redux delta)
    prep1_kernel<<<192, 256>>>(W1);
    prep2_kernel<<<256, 256>>>(W2);
    fps_kernel<<<Bq, 512>>>(xyz, out);
    knng_kernel<<<dim3(Sq, Bq), 256>>>(xyz, points);
    gemm_kernel<0><<<NTILES, 256, SM_TOT>>>();
    stats_final<<<256, 256>>>(0, g1, bt1);
    gemm_kernel<1><<<NTILES, 256, SM_TOT>>>();
    stats_final<<<256, 256>>>(1, g2, bt2);
    final_kernel<<<Bq*Sq, 256>>>(out);
}

// round 12
// speedup vs baseline: 1.1088x; 1.0562x over previous
#include <cuda_runtime.h>
#include <cuda_fp16.h>
#include <math_constants.h>
#include <cstdint>

// Problem constants
#define Bq   16
#define Nq   4096
#define Dq   128
#define Sq   1024
#define Kq   16
#define CIN  131            // 3 + D
#define KT1  192            // layer-1 K padded (6 chunks of 32)
#define KT2  256            // layer-2 K (8 chunks of 32)
#define NT   (Bq*Sq*Kq)     // 262144 tokens
#define NTILES (NT/128)     // 2048 n-tiles
#define OUT_XYZ (Bq*Sq*3)

// ---------------- static device scratch -------------------------------------
__device__ float d_newxyz[Bq*Sq*3];
__device__ __align__(16) __half d_W1h[256*KT1];              // W hi plane only
__device__ __align__(16) __half d_W2h[256*KT2];
__device__ __align__(16) __half d_Fh[(size_t)NT*KT1], d_Fl[(size_t)NT*KT1];
__device__ __align__(16) float d_Y1[(size_t)NT*256];         // layer1 raw acc [n][o]
__device__ __align__(16) float d_qmax[Bq*Sq*256], d_qmin[Bq*Sq*256];
__device__ float d_psY[256*NTILES], d_psQ[256*NTILES];       // transposed partials
__device__ float d_aA[2*256], d_cA[2*256];

// ---------------- helpers ----------------------------------------------------
__device__ __forceinline__ float sqdist(float px, float py, float pz,
                                        float cx, float cy, float cz) {
    float dx = px - cx, dy = py - cy, dz = pz - cz;
    return __fadd_rn(__fadd_rn(__fmul_rn(dx, dx), __fmul_rn(dy, dy)),
                     __fmul_rn(dz, dz));
}

__device__ __forceinline__ void split2h(float v, __half& h, __half& l) {
    h = __float2half_rn(v);
    l = __float2half_rn(v - __half2float(h));
}

__device__ __forceinline__ unsigned long long umax64(unsigned long long a,
                                                     unsigned long long b) {
    return a > b ? a : b;
}

__device__ __forceinline__ void mma16816h(float d[4], uint32_t a0, uint32_t a1,
                                          uint32_t a2, uint32_t a3,
                                          uint32_t b0, uint32_t b1) {
    asm volatile(
        "mma.sync.aligned.m16n8k16.row.col.f32.f16.f16.f32 "
        "{%0,%1,%2,%3}, {%4,%5,%6,%7}, {%8,%9}, {%0,%1,%2,%3};"
        : "+f"(d[0]), "+f"(d[1]), "+f"(d[2]), "+f"(d[3])
        : "r"(a0), "r"(a1), "r"(a2), "r"(a3), "r"(b0), "r"(b1));
}

#define CP16(dst, src) \
    asm volatile("cp.async.cg.shared.global [%0], [%1], 16;" :: "r"(dst), "l"(src) : "memory")
#define CP_COMMIT() asm volatile("cp.async.commit_group;" ::: "memory")
#define CP_WAIT1()  asm volatile("cp.async.wait_group 1;" ::: "memory")
#define CP_WAIT0()  asm volatile("cp.async.wait_group 0;" ::: "memory")

// ---------------------------- FPS (R11 version, verbatim) ----------------------
__global__ void __launch_bounds__(512) fps_kernel(const float* __restrict__ xyz,
                                                  float* __restrict__ out) {
    int b = blockIdx.x, t = threadIdx.x;
    const float* base = xyz + (size_t)b * Nq * 3;
    float px[8], py[8], pz[8], dist[8];
#pragma unroll
    for (int i = 0; i < 8; i++) {
        int n = i * 512 + t;
        px[i] = base[n*3+0]; py[i] = base[n*3+1]; pz[i] = base[n*3+2];
        dist[i] = 1e10f;
    }
    __shared__ unsigned long long wred[2][16];
    int lane = t & 31, w = t >> 5;
    int far = 0;
    for (int it = 0; it < Sq; it++) {
        float cx = __ldg(base + far*3 + 0);
        float cy = __ldg(base + far*3 + 1);
        float cz = __ldg(base + far*3 + 2);
        if (t == 0) {
            int o = (b*Sq + it) * 3;
            d_newxyz[o] = cx; d_newxyz[o+1] = cy; d_newxyz[o+2] = cz;
            out[o] = cx; out[o+1] = cy; out[o+2] = cz;
        }
        unsigned long long best = 0ULL;
#pragma unroll
        for (int i = 0; i < 8; i++) {
            float d  = sqdist(px[i], py[i], pz[i], cx, cy, cz);
            float dd = fminf(dist[i], d);
            dist[i]  = dd;
            unsigned long long key =
                ((unsigned long long)__float_as_uint(dd) << 32) |
                (unsigned)~(unsigned)(i*512 + t);
            if (key > best) best = key;
        }
#pragma unroll
        for (int off = 16; off > 0; off >>= 1) {
            unsigned long long o2 = __shfl_down_sync(0xFFFFFFFFu, best, off);
            if (o2 > best) best = o2;
        }
        if (lane == 0) wred[it & 1][w] = best;
        __syncthreads();
        const unsigned long long* wr = wred[it & 1];
        unsigned long long t0 = umax64(wr[0],  wr[1]);
        unsigned long long t1 = umax64(wr[2],  wr[3]);
        unsigned long long t2 = umax64(wr[4],  wr[5]);
        unsigned long long t3 = umax64(wr[6],  wr[7]);
        unsigned long long t4 = umax64(wr[8],  wr[9]);
        unsigned long long t5 = umax64(wr[10], wr[11]);
        unsigned long long t6 = umax64(wr[12], wr[13]);
        unsigned long long t7 = umax64(wr[14], wr[15]);
        unsigned long long s0 = umax64(umax64(t0, t1), umax64(t2, t3));
        unsigned long long s1 = umax64(umax64(t4, t5), umax64(t6, t7));
        far = (int)(~(unsigned)umax64(s0, s1));
    }
}

// ---- fused kNN + gather + fp16-split (register distances, dead-mask rescan) ----
__global__ void __launch_bounds__(256) knng_kernel(const float* __restrict__ xyz,
                                                   const float* __restrict__ points) {
    int s = blockIdx.x, b = blockIdx.y, t = threadIdx.x;
    const float* base = xyz + (size_t)b * Nq * 3;
    int qo = b*Sq + s;
    float cx = d_newxyz[qo*3], cy = d_newxyz[qo*3+1], cz = d_newxyz[qo*3+2];

    __shared__ unsigned long long wred[8];
    __shared__ unsigned long long winner;
    __shared__ int idx[Kq];

    // pass 1: distances in REGISTERS + per-thread running lexicographic min
    float dreg[16];
    unsigned bd = 0xFFFFFFFFu, bi = 0u;
#pragma unroll
    for (int j = 0; j < 16; j++) {
        int n = j*256 + t;
        float d = sqdist(base[n*3], base[n*3+1], base[n*3+2], cx, cy, cz);
        dreg[j] = d;
        unsigned ud = __float_as_uint(d);
        if (ud < bd) { bd = ud; bi = (unsigned)n; }   // ties keep earlier n
    }
    unsigned dead = 0u;
    int lane = t & 31, w = t >> 5;
    for (int r = 0; r < Kq; r++) {
        unsigned wd = __reduce_min_sync(0xFFFFFFFFu, bd);
        unsigned ci = (bd == wd) ? bi : 0xFFFFFFFFu;
        unsigned wi = __reduce_min_sync(0xFFFFFFFFu, ci);
        if (lane == 0) wred[w] = ((unsigned long long)wd << 32) | wi;
        __syncthreads();
        if (t == 0) {
            unsigned long long m = wred[0];
#pragma unroll
            for (int i = 1; i < 8; i++) if (wred[i] < m) m = wred[i];
            winner = m;
            idx[r] = (int)(unsigned)m;
        }
        __syncthreads();
        if (r < Kq-1) {
            unsigned widx = (unsigned)winner;
            if ((widx & 255u) == (unsigned)t) {
                dead |= 1u << ((widx - (unsigned)t) >> 8);
                bd = 0xFFFFFFFFu; bi = 0u;
#pragma unroll
                for (int j = 0; j < 16; j++) {
                    unsigned ud = (dead >> j & 1u) ? 0xFFFFFFFFu
                                                   : __float_as_uint(dreg[j]);
                    if (ud < bd) { bd = ud; bi = (unsigned)(j*256 + t); }
                }
            }
        }
    }
    __syncthreads();
    // gather + split
    const float* pbase = points + (size_t)b * Nq * Dq;
    size_t rowb = (size_t)qo * Kq * KT1;
    for (int e = t; e < Kq*KT1; e += 256) {
        int k = e / KT1, c = e - k*KT1;
        int n = idx[k];
        float v = 0.0f;
        if (c < 3) v = base[n*3 + c] - ((c == 0) ? cx : ((c == 1) ? cy : cz));
        else if (c < CIN) v = pbase[(size_t)n*Dq + (c-3)];
        __half h, l; split2h(v, h, l);
        d_Fh[rowb + e] = h; d_Fl[rowb + e] = l;
    }
}

// ------------------- weight fp16 (hi only) + pad -------------------------------
__global__ void prep1_kernel(const float* __restrict__ W1) {
    int i = blockIdx.x * 256 + threadIdx.x;
    if (i < 256*KT1) {
        int o = i / KT1, c = i - o*KT1;
        d_W1h[i] = __float2half_rn((c < CIN) ? W1[o*CIN + c] : 0.0f);
    }
}

__global__ void prep2_kernel(const float* __restrict__ W2) {
    int i = blockIdx.x * 256 + threadIdx.x;
    if (i < 256*KT2) {
        int o = i >> 8, c = i & 255;
        d_W2h[i] = __float2half_rn(W2[o*256 + c]);
    }
}

// ---------- pipelined HMMA fp16 2-MMA GEMM (triple buffer, 1 sync) -------------
#define ST  40
#define APL (128*ST*2)            // 10240 B per A plane
#define WPL (256*ST*2)            // 20480 B for W hi plane
#define OFF_ALO APL
#define OFF_WHI (2*APL)
#define BUFSZ   (2*APL + WPL)     // 40960
#define SM_YS   (3*BUFSZ)
#define SM_QS   (SM_YS + 1024)
#define SM_A1   (SM_QS + 1024)
#define SM_C1   (SM_A1 + 1024)
#define SM_TOT  (SM_C1 + 1024)    // 126976

__device__ __forceinline__ void stageW(char* dst, const __half* __restrict__ Wh,
                                       int KT, int kb, int tid) {
#pragma unroll
    for (int it = 0; it < 4; it++) {
        int u = tid + it*256, o = u >> 2, q = u & 3;
        size_t go = (size_t)o*KT + kb*32 + q*8;
        uint32_t sh = (uint32_t)__cvta_generic_to_shared(dst + OFF_WHI + (o*ST + q*8)*2);
        CP16(sh, Wh + go);
    }
}

__device__ __forceinline__ void stageA0(char* dst, int nbase, int kb, int tid) {
#pragma unroll
    for (int it = 0; it < 2; it++) {
        int u = tid + it*256, r = u >> 2, q = u & 3;
        size_t go = (size_t)(nbase + r)*KT1 + kb*32 + q*8;
        uint32_t sh = (uint32_t)__cvta_generic_to_shared(dst + (r*ST + q*8)*2);
        uint32_t sl = (uint32_t)__cvta_generic_to_shared(dst + OFF_ALO + (r*ST + q*8)*2);
        CP16(sh, d_Fh + go);
        CP16(sl, d_Fl + go);
    }
}

__device__ __forceinline__ void prefA1(float4 rg[4], int nbase, int kb, int tid) {
#pragma unroll
    for (int it = 0; it < 2; it++) {
        int u = tid + it*256, r = u >> 2, q = u & 3;
        const float* src = d_Y1 + (size_t)(nbase + r)*256 + kb*32 + q*8;
        rg[it*2]   = *(const float4*)src;
        rg[it*2+1] = *(const float4*)(src + 4);
    }
}

__device__ __forceinline__ void stageA1(char* dst, const float4 rg[4], int kb,
                                        int tid, const float* sA, const float* sC) {
#pragma unroll
    for (int it = 0; it < 2; it++) {
        int u = tid + it*256, r = u >> 2, q = u & 3;
        int cb = kb*32 + q*8;
        float vs[8] = {rg[it*2].x, rg[it*2].y, rg[it*2].z, rg[it*2].w,
                       rg[it*2+1].x, rg[it*2+1].y, rg[it*2+1].z, rg[it*2+1].w};
        uint32_t hp[4], lp[4];
#pragma unroll
        for (int jp = 0; jp < 4; jp++) {
            float v0 = fmaxf(fmaf(vs[2*jp],   sA[cb+2*jp],   sC[cb+2*jp]),   0.0f);
            float v1 = fmaxf(fmaf(vs[2*jp+1], sA[cb+2*jp+1], sC[cb+2*jp+1]), 0.0f);
            __half h0, l0, h1, l1;
            split2h(v0, h0, l0); split2h(v1, h1, l1);
            hp[jp] = (uint32_t)__half_as_ushort(h0) |
                     ((uint32_t)__half_as_ushort(h1) << 16);
            lp[jp] = (uint32_t)__half_as_ushort(l0) |
                     ((uint32_t)__half_as_ushort(l1) << 16);
        }
        *(uint4*)(dst + (r*ST + q*8)*2)           = make_uint4(hp[0], hp[1], hp[2], hp[3]);
        *(uint4*)(dst + OFF_ALO + (r*ST + q*8)*2) = make_uint4(lp[0], lp[1], lp[2], lp[3]);
    }
}

__device__ __forceinline__ void compute_chunk(const char* smc, int wn, int wo,
                                              int g, int m, float acc[4][8][4]) {
#pragma unroll
    for (int ks = 0; ks < 2; ks++) {
        int cb = ks*16 + 2*m;
        uint32_t ah[4][4], al[4][4];
#pragma unroll
        for (int i = 0; i < 4; i++) {
            int r0 = wn*64 + i*16 + g;
            ah[i][0] = *(const uint32_t*)(smc + (r0*ST + cb)*2);
            ah[i][1] = *(const uint32_t*)(smc + ((r0+8)*ST + cb)*2);
            ah[i][2] = *(const uint32_t*)(smc + (r0*ST + cb + 8)*2);
            ah[i][3] = *(const uint32_t*)(smc + ((r0+8)*ST + cb + 8)*2);
            al[i][0] = *(const uint32_t*)(smc + OFF_ALO + (r0*ST + cb)*2);
            al[i][1] = *(const uint32_t*)(smc + OFF_ALO + ((r0+8)*ST + cb)*2);
            al[i][2] = *(const uint32_t*)(smc + OFF_ALO + (r0*ST + cb + 8)*2);
            al[i][3] = *(const uint32_t*)(smc + OFF_ALO + ((r0+8)*ST + cb + 8)*2);
        }
#pragma unroll
        for (int j = 0; j < 8; j++) {
            int ro = wo*64 + j*8 + g;
            uint32_t bh0 = *(const uint32_t*)(smc + OFF_WHI + (ro*ST + cb)*2);
            uint32_t bh1 = *(const uint32_t*)(smc + OFF_WHI + (ro*ST + cb + 8)*2);
#pragma unroll
            for (int i = 0; i < 4; i++) {
                mma16816h(acc[i][j], ah[i][0], ah[i][1], ah[i][2], ah[i][3], bh0, bh1);
                mma16816h(acc[i][j], al[i][0], al[i][1], al[i][2], al[i][3], bh0, bh1);
            }
        }
    }
}

template<int LAYER>
__global__ void __launch_bounds__(256, 1) gemm_kernel() {
    const __half* Wh = LAYER ? d_W2h : d_W1h;
    const int KT  = LAYER ? KT2 : KT1;
    const int nKB = KT >> 5;

    extern __shared__ char sm[];
    int tid = threadIdx.x, lane = tid & 31, wid = tid >> 5;
    int g = lane >> 2, m = lane & 3;
    int wn = wid & 1, wo = wid >> 1;
    int nbase = blockIdx.x * 128;

    float* sA = (float*)(sm + SM_A1);
    float* sC = (float*)(sm + SM_C1);
    if (LAYER) { sA[tid] = d_aA[tid]; sC[tid] = d_cA[tid]; }

    float acc[4][8][4];
#pragma unroll
    for (int i = 0; i < 4; i++)
#pragma unroll
        for (int j = 0; j < 8; j++)
#pragma unroll
            for (int e = 0; e < 4; e++) acc[i][j][e] = 0.0f;

    float4 rg[4];
    // prologue: stage chunk 0 into buffer 0
    if (LAYER) {
        __syncthreads();            // sA/sC visible
        prefA1(rg, nbase, 0, tid);
        stageA1(sm, rg, 0, tid, sA, sC);
    } else {
        stageA0(sm, nbase, 0, tid);
    }
    stageW(sm, Wh, KT, 0, tid);
    CP_COMMIT();
    if (LAYER) prefA1(rg, nbase, 1, tid);

    // triple-buffered mainloop: ONE __syncthreads per chunk
    for (int kb = 0; kb < nKB; kb++) {
        char* cur = sm + (kb % 3) * BUFSZ;
        char* nxt = sm + ((kb + 1) % 3) * BUFSZ;
        if (kb + 1 < nKB) {
            if (LAYER) {
                stageA1(nxt, rg, kb + 1, tid, sA, sC);
                if (kb + 2 < nKB) prefA1(rg, nbase, kb + 2, tid);
            } else {
                stageA0(nxt, nbase, kb + 1, tid);
            }
            stageW(nxt, Wh, KT, kb + 1, tid);
            CP_COMMIT();
            CP_WAIT1();
        } else {
            CP_WAIT0();
        }
        __syncthreads();
        compute_chunk(cur, wn, wo, g, m, acc);
    }
    __syncthreads();

    // ---------------- epilogue -------------------------------------------------
    float* ys = (float*)(sm + SM_YS);
    float* qs = (float*)(sm + SM_QS);
    ys[tid] = 0.0f; qs[tid] = 0.0f;
    __syncthreads();

    float sc[8][2], qc[8][2];
#pragma unroll
    for (int j = 0; j < 8; j++) { sc[j][0]=sc[j][1]=qc[j][0]=qc[j][1]=0.0f; }

#pragma unroll
    for (int i = 0; i < 4; i++) {
        int r0 = nbase + wn*64 + i*16 + g;
#pragma unroll
        for (int j = 0; j < 8; j++) {
            int col = wo*64 + j*8 + 2*m;
            float v0 = acc[i][j][0], v1 = acc[i][j][1];
            float v2 = acc[i][j][2], v3 = acc[i][j][3];
            if (!LAYER) {
                *(float2*)(d_Y1 + (size_t)r0*256 + col)     = make_float2(v0, v1);
                *(float2*)(d_Y1 + (size_t)(r0+8)*256 + col) = make_float2(v2, v3);
            } else {
                // per-query max/min over k (query = 16 consecutive tokens)
                float mxa = fmaxf(v0, v2), mxb = fmaxf(v1, v3);
                float mna = fminf(v0, v2), mnb = fminf(v1, v3);
#pragma unroll
                for (int off = 4; off < 32; off <<= 1) {
                    mxa = fmaxf(mxa, __shfl_xor_sync(0xFFFFFFFFu, mxa, off));
                    mxb = fmaxf(mxb, __shfl_xor_sync(0xFFFFFFFFu, mxb, off));
                    mna = fminf(mna, __shfl_xor_sync(0xFFFFFFFFu, mna, off));
                    mnb = fminf(mnb, __shfl_xor_sync(0xFFFFFFFFu, mnb, off));
                }
                if (g == 0) {
                    int q = blockIdx.x*8 + wn*4 + i;
                    *(float2*)(d_qmax + (size_t)q*256 + col) = make_float2(mxa, mxb);
                    *(float2*)(d_qmin + (size_t)q*256 + col) = make_float2(mna, mnb);
                }
            }
            sc[j][0] += v0 + v2;       sc[j][1] += v1 + v3;
            qc[j][0] += v0*v0 + v2*v2; qc[j][1] += v1*v1 + v3*v3;
        }
    }
#pragma unroll
    for (int j = 0; j < 8; j++)
#pragma unroll
        for (int e = 0; e < 2; e++) {
#pragma unroll
            for (int off = 4; off < 32; off <<= 1) {
                sc[j][e] += __shfl_xor_sync(0xFFFFFFFFu, sc[j][e], off);
                qc[j][e] += __shfl_xor_sync(0xFFFFFFFFu, qc[j][e], off);
            }
        }
    if (wn == 0 && lane < 4) {
#pragma unroll
        for (int j = 0; j < 8; j++) {
            int col = wo*64 + j*8 + 2*lane;
            ys[col] = sc[j][0];   ys[col+1] = sc[j][1];
            qs[col] = qc[j][0];   qs[col+1] = qc[j][1];
        }
    }
    __syncthreads();
    if (wn == 1 && lane < 4) {
#pragma unroll
        for (int j = 0; j < 8; j++) {
            int col = wo*64 + j*8 + 2*lane;
            ys[col] += sc[j][0];  ys[col+1] += sc[j][1];
            qs[col] += qc[j][0];  qs[col+1] += qc[j][1];
        }
    }
    __syncthreads();
    d_psY[(size_t)tid*NTILES + blockIdx.x] = ys[tid];
    d_psQ[(size_t)tid*NTILES + blockIdx.x] = qs[tid];
}

// ---------------- BN stats finalize (256 blocks, coalesced) --------------------
__global__ void __launch_bounds__(256) stats_final(int layer,
                                                   const float* __restrict__ g,
                                                   const float* __restrict__ bt) {
    int o = blockIdx.x, t = threadIdx.x;
    float s = 0.0f, q = 0.0f;
    for (int i = t; i < NTILES; i += 256) {
        s += d_psY[(size_t)o*NTILES + i];
        q += d_psQ[(size_t)o*NTILES + i];
    }
    __shared__ float ss[8], sq[8];
#pragma unroll
    for (int off = 16; off > 0; off >>= 1) {
        s += __shfl_down_sync(0xFFFFFFFFu, s, off);
        q += __shfl_down_sync(0xFFFFFFFFu, q, off);
    }
    if ((t & 31) == 0) { ss[t >> 5] = s; sq[t >> 5] = q; }
    __syncthreads();
    if (t == 0) {
        float S = 0.0f, Q = 0.0f;
#pragma unroll
        for (int i = 0; i < 8; i++) { S += ss[i]; Q += sq[i]; }
        float mean = S * (1.0f / NT);
        float var  = Q * (1.0f / NT) - mean*mean;
        float av = rsqrtf(var + 1e-5f) * g[o];
        d_aA[layer*256 + o] = av;
        d_cA[layer*256 + o] = bt[o] - mean * av;   // bias-free (cancels in BN)
    }
}

// ----------- final: pick max/min by sign(a2), affine + relu --------------------
__global__ void __launch_bounds__(256) final_kernel(float* __restrict__ out) {
    size_t idx = (size_t)blockIdx.x * 256 + threadIdx.x;
    int o = threadIdx.x;
    float a = d_aA[256 + o], c = d_cA[256 + o];
    float v = (a >= 0.0f) ? d_qmax[idx] : d_qmin[idx];
    out[OUT_XYZ + idx] = fmaxf(fmaf(v, a, c), 0.0f);
}

// ------------------------------- launch ----------------------------------------
extern "C" void kernel_launch(void* const* d_in, const int* in_sizes, int n_in,
                              void* d_out, int out_size) {
    const float* xyz    = (const float*)d_in[0];
    const float* points = (const float*)d_in[1];
    const float* W1  = (const float*)d_in[2];
    const float* g1  = (const float*)d_in[4];
    const float* bt1 = (const float*)d_in[5];
    const float* W2  = (const float*)d_in[6];
    const float* g2  = (const float*)d_in[8];
    const float* bt2 = (const float*)d_in[9];
    float* out = (float*)d_out;

    cudaFuncSetAttribute(gemm_kernel<0>, cudaFuncAttributeMaxDynamicSharedMemorySize, SM_TOT);
    cudaFuncSetAttribute(gemm_kernel<1>, cudaFuncAttributeMaxDynamicSharedMemorySize, SM_TOT);

    // keep knng as the 4th launch so ncu captures it (verify the reg-distance delta)
    prep1_kernel<<<192, 256>>>(W1);
    prep2_kernel<<<256, 256>>>(W2);
    fps_kernel<<<Bq, 512>>>(xyz, out);
    knng_kernel<<<dim3(Sq, Bq), 256>>>(xyz, points);
    gemm_kernel<0><<<NTILES, 256, SM_TOT>>>();
    stats_final<<<256, 256>>>(0, g1, bt1);
    gemm_kernel<1><<<NTILES, 256, SM_TOT>>>();
    stats_final<<<256, 256>>>(1, g2, bt2);
    final_kernel<<<Bq*Sq, 256>>>(out);
}

// round 13
// speedup vs baseline: 1.1531x; 1.0399x over previous
#include <cuda_runtime.h>
#include <cuda_fp16.h>
#include <math_constants.h>
#include <cstdint>

// Problem constants
#define Bq   16
#define Nq   4096
#define Dq   128
#define Sq   1024
#define Kq   16
#define CIN  131            // 3 + D
#define KT1  192            // layer-1 K padded (6 chunks of 32)
#define KT2  256            // layer-2 K (8 chunks of 32)
#define NT   (Bq*Sq*Kq)     // 262144 tokens
#define NTILES (NT/128)     // 2048 n-tiles
#define OUT_XYZ (Bq*Sq*3)

// ---------------- static device scratch -------------------------------------
__device__ float d_newxyz[Bq*Sq*3];
__device__ __align__(16) __half d_W1h[256*KT1];              // W hi plane only
__device__ __align__(16) __half d_W2h[256*KT2];
__device__ __align__(16) __half d_Fh[(size_t)NT*KT1], d_Fl[(size_t)NT*KT1];
__device__ __align__(16) float d_Y1[(size_t)NT*256];         // layer1 raw acc [n][o]
__device__ __align__(16) float d_qmax[Bq*Sq*256], d_qmin[Bq*Sq*256];
__device__ float d_psY[256*NTILES], d_psQ[256*NTILES];       // transposed partials
__device__ float d_aA[2*256], d_cA[2*256];

// ---------------- helpers ----------------------------------------------------
__device__ __forceinline__ float sqdist(float px, float py, float pz,
                                        float cx, float cy, float cz) {
    float dx = px - cx, dy = py - cy, dz = pz - cz;
    return __fadd_rn(__fadd_rn(__fmul_rn(dx, dx), __fmul_rn(dy, dy)),
                     __fmul_rn(dz, dz));
}

__device__ __forceinline__ void split2h(float v, __half& h, __half& l) {
    h = __float2half_rn(v);
    l = __float2half_rn(v - __half2float(h));
}

__device__ __forceinline__ unsigned long long umax64(unsigned long long a,
                                                     unsigned long long b) {
    return a > b ? a : b;
}

__device__ __forceinline__ void mma16816h(float d[4], uint32_t a0, uint32_t a1,
                                          uint32_t a2, uint32_t a3,
                                          uint32_t b0, uint32_t b1) {
    asm volatile(
        "mma.sync.aligned.m16n8k16.row.col.f32.f16.f16.f32 "
        "{%0,%1,%2,%3}, {%4,%5,%6,%7}, {%8,%9}, {%0,%1,%2,%3};"
        : "+f"(d[0]), "+f"(d[1]), "+f"(d[2]), "+f"(d[3])
        : "r"(a0), "r"(a1), "r"(a2), "r"(a3), "r"(b0), "r"(b1));
}

#define CP16(dst, src) \
    asm volatile("cp.async.cg.shared.global [%0], [%1], 16;" :: "r"(dst), "l"(src) : "memory")
#define CP_COMMIT() asm volatile("cp.async.commit_group;" ::: "memory")
#define CP_WAIT1()  asm volatile("cp.async.wait_group 1;" ::: "memory")
#define CP_WAIT0()  asm volatile("cp.async.wait_group 0;" ::: "memory")

// ---------------------------- FPS (R11 version, verbatim) ----------------------
__global__ void __launch_bounds__(512) fps_kernel(const float* __restrict__ xyz,
                                                  float* __restrict__ out) {
    int b = blockIdx.x, t = threadIdx.x;
    const float* base = xyz + (size_t)b * Nq * 3;
    float px[8], py[8], pz[8], dist[8];
#pragma unroll
    for (int i = 0; i < 8; i++) {
        int n = i * 512 + t;
        px[i] = base[n*3+0]; py[i] = base[n*3+1]; pz[i] = base[n*3+2];
        dist[i] = 1e10f;
    }
    __shared__ unsigned long long wred[2][16];
    int lane = t & 31, w = t >> 5;
    int far = 0;
    for (int it = 0; it < Sq; it++) {
        float cx = __ldg(base + far*3 + 0);
        float cy = __ldg(base + far*3 + 1);
        float cz = __ldg(base + far*3 + 2);
        if (t == 0) {
            int o = (b*Sq + it) * 3;
            d_newxyz[o] = cx; d_newxyz[o+1] = cy; d_newxyz[o+2] = cz;
            out[o] = cx; out[o+1] = cy; out[o+2] = cz;
        }
        unsigned long long best = 0ULL;
#pragma unroll
        for (int i = 0; i < 8; i++) {
            float d  = sqdist(px[i], py[i], pz[i], cx, cy, cz);
            float dd = fminf(dist[i], d);
            dist[i]  = dd;
            unsigned long long key =
                ((unsigned long long)__float_as_uint(dd) << 32) |
                (unsigned)~(unsigned)(i*512 + t);
            if (key > best) best = key;
        }
#pragma unroll
        for (int off = 16; off > 0; off >>= 1) {
            unsigned long long o2 = __shfl_down_sync(0xFFFFFFFFu, best, off);
            if (o2 > best) best = o2;
        }
        if (lane == 0) wred[it & 1][w] = best;
        __syncthreads();
        const unsigned long long* wr = wred[it & 1];
        unsigned long long t0 = umax64(wr[0],  wr[1]);
        unsigned long long t1 = umax64(wr[2],  wr[3]);
        unsigned long long t2 = umax64(wr[4],  wr[5]);
        unsigned long long t3 = umax64(wr[6],  wr[7]);
        unsigned long long t4 = umax64(wr[8],  wr[9]);
        unsigned long long t5 = umax64(wr[10], wr[11]);
        unsigned long long t6 = umax64(wr[12], wr[13]);
        unsigned long long t7 = umax64(wr[14], wr[15]);
        unsigned long long s0 = umax64(umax64(t0, t1), umax64(t2, t3));
        unsigned long long s1 = umax64(umax64(t4, t5), umax64(t6, t7));
        far = (int)(~(unsigned)umax64(s0, s1));
    }
}

// ---- fused kNN + gather + fp16-split (R11 selection: smem ds + redux.min) -----
__global__ void __launch_bounds__(256) knng_kernel(const float* __restrict__ xyz,
                                                   const float* __restrict__ points) {
    int s = blockIdx.x, b = blockIdx.y, t = threadIdx.x;
    const float* base = xyz + (size_t)b * Nq * 3;
    int qo = b*Sq + s;
    float cx = d_newxyz[qo*3], cy = d_newxyz[qo*3+1], cz = d_newxyz[qo*3+2];

    __shared__ float ds[Nq];
    __shared__ unsigned long long wred[8];
    __shared__ unsigned long long winner;
    __shared__ int idx[Kq];

    // pass 1: distances + per-thread running lexicographic min (d, n)
    unsigned bd = 0xFFFFFFFFu, bi = 0u;
#pragma unroll 4
    for (int j = 0; j < 16; j++) {
        int n = j*256 + t;
        float d = sqdist(base[n*3], base[n*3+1], base[n*3+2], cx, cy, cz);
        ds[n] = d;
        unsigned ud = __float_as_uint(d);
        if (ud < bd) { bd = ud; bi = (unsigned)n; }   // ties keep earlier n
    }
    int lane = t & 31, w = t >> 5;
    for (int r = 0; r < Kq; r++) {
        // warp lexicographic min via two u32 redux ops
        unsigned wd = __reduce_min_sync(0xFFFFFFFFu, bd);
        unsigned ci = (bd == wd) ? bi : 0xFFFFFFFFu;
        unsigned wi = __reduce_min_sync(0xFFFFFFFFu, ci);
        if (lane == 0) wred[w] = ((unsigned long long)wd << 32) | wi;
        __syncthreads();
        if (t == 0) {
            unsigned long long m = wred[0];
#pragma unroll
            for (int i = 1; i < 8; i++) if (wred[i] < m) m = wred[i];
            winner = m;
            idx[r] = (int)(unsigned)m;
        }
        __syncthreads();
        if (r < Kq-1) {
            unsigned widx = (unsigned)winner;
            if ((widx & 255u) == (unsigned)t) {
                ds[widx] = CUDART_INF_F;
                bd = 0xFFFFFFFFu; bi = 0u;
#pragma unroll 4
                for (int j = 0; j < 16; j++) {
                    int n = j*256 + t;
                    unsigned ud = __float_as_uint(ds[n]);
                    if (ud < bd) { bd = ud; bi = (unsigned)n; }
                }
            }
        }
    }
    __syncthreads();
    // gather + split
    const float* pbase = points + (size_t)b * Nq * Dq;
    size_t rowb = (size_t)qo * Kq * KT1;
    for (int e = t; e < Kq*KT1; e += 256) {
        int k = e / KT1, c = e - k*KT1;
        int n = idx[k];
        float v = 0.0f;
        if (c < 3) v = base[n*3 + c] - ((c == 0) ? cx : ((c == 1) ? cy : cz));
        else if (c < CIN) v = pbase[(size_t)n*Dq + (c-3)];
        __half h, l; split2h(v, h, l);
        d_Fh[rowb + e] = h; d_Fl[rowb + e] = l;
    }
}

// ------------------- weight fp16 (hi only) + pad -------------------------------
__global__ void prep1_kernel(const float* __restrict__ W1) {
    int i = blockIdx.x * 256 + threadIdx.x;
    if (i < 256*KT1) {
        int o = i / KT1, c = i - o*KT1;
        d_W1h[i] = __float2half_rn((c < CIN) ? W1[o*CIN + c] : 0.0f);
    }
}

__global__ void prep2_kernel(const float* __restrict__ W2) {
    int i = blockIdx.x * 256 + threadIdx.x;
    if (i < 256*KT2) {
        int o = i >> 8, c = i & 255;
        d_W2h[i] = __float2half_rn(W2[o*256 + c]);
    }
}

// ---------- pipelined HMMA fp16 2-MMA GEMM (triple buffer, 1 sync) -------------
#define ST  40
#define APL (128*ST*2)            // 10240 B per A plane
#define WPL (256*ST*2)            // 20480 B for W hi plane
#define OFF_ALO APL
#define OFF_WHI (2*APL)
#define BUFSZ   (2*APL + WPL)     // 40960
#define SM_YS   (3*BUFSZ)
#define SM_QS   (SM_YS + 1024)
#define SM_A1   (SM_QS + 1024)
#define SM_C1   (SM_A1 + 1024)
#define SM_TOT  (SM_C1 + 1024)    // 126976

__device__ __forceinline__ void stageW(char* dst, const __half* __restrict__ Wh,
                                       int KT, int kb, int tid) {
#pragma unroll
    for (int it = 0; it < 4; it++) {
        int u = tid + it*256, o = u >> 2, q = u & 3;
        size_t go = (size_t)o*KT + kb*32 + q*8;
        uint32_t sh = (uint32_t)__cvta_generic_to_shared(dst + OFF_WHI + (o*ST + q*8)*2);
        CP16(sh, Wh + go);
    }
}

__device__ __forceinline__ void stageA0(char* dst, int nbase, int kb, int tid) {
#pragma unroll
    for (int it = 0; it < 2; it++) {
        int u = tid + it*256, r = u >> 2, q = u & 3;
        size_t go = (size_t)(nbase + r)*KT1 + kb*32 + q*8;
        uint32_t sh = (uint32_t)__cvta_generic_to_shared(dst + (r*ST + q*8)*2);
        uint32_t sl = (uint32_t)__cvta_generic_to_shared(dst + OFF_ALO + (r*ST + q*8)*2);
        CP16(sh, d_Fh + go);
        CP16(sl, d_Fl + go);
    }
}

__device__ __forceinline__ void prefA1(float4 rg[4], int nbase, int kb, int tid) {
#pragma unroll
    for (int it = 0; it < 2; it++) {
        int u = tid + it*256, r = u >> 2, q = u & 3;
        const float* src = d_Y1 + (size_t)(nbase + r)*256 + kb*32 + q*8;
        rg[it*2]   = *(const float4*)src;
        rg[it*2+1] = *(const float4*)(src + 4);
    }
}

__device__ __forceinline__ void stageA1(char* dst, const float4 rg[4], int kb,
                                        int tid, const float* sA, const float* sC) {
#pragma unroll
    for (int it = 0; it < 2; it++) {
        int u = tid + it*256, r = u >> 2, q = u & 3;
        int cb = kb*32 + q*8;
        float vs[8] = {rg[it*2].x, rg[it*2].y, rg[it*2].z, rg[it*2].w,
                       rg[it*2+1].x, rg[it*2+1].y, rg[it*2+1].z, rg[it*2+1].w};
        uint32_t hp[4], lp[4];
#pragma unroll
        for (int jp = 0; jp < 4; jp++) {
            float v0 = fmaxf(fmaf(vs[2*jp],   sA[cb+2*jp],   sC[cb+2*jp]),   0.0f);
            float v1 = fmaxf(fmaf(vs[2*jp+1], sA[cb+2*jp+1], sC[cb+2*jp+1]), 0.0f);
            __half h0, l0, h1, l1;
            split2h(v0, h0, l0); split2h(v1, h1, l1);
            hp[jp] = (uint32_t)__half_as_ushort(h0) |
                     ((uint32_t)__half_as_ushort(h1) << 16);
            lp[jp] = (uint32_t)__half_as_ushort(l0) |
                     ((uint32_t)__half_as_ushort(l1) << 16);
        }
        *(uint4*)(dst + (r*ST + q*8)*2)           = make_uint4(hp[0], hp[1], hp[2], hp[3]);
        *(uint4*)(dst + OFF_ALO + (r*ST + q*8)*2) = make_uint4(lp[0], lp[1], lp[2], lp[3]);
    }
}

__device__ __forceinline__ void compute_chunk(const char* smc, int wn, int wo,
                                              int g, int m, float acc[4][8][4]) {
#pragma unroll
    for (int ks = 0; ks < 2; ks++) {
        int cb = ks*16 + 2*m;
        uint32_t ah[4][4], al[4][4];
#pragma unroll
        for (int i = 0; i < 4; i++) {
            int r0 = wn*64 + i*16 + g;
            ah[i][0] = *(const uint32_t*)(smc + (r0*ST + cb)*2);
            ah[i][1] = *(const uint32_t*)(smc + ((r0+8)*ST + cb)*2);
            ah[i][2] = *(const uint32_t*)(smc + (r0*ST + cb + 8)*2);
            ah[i][3] = *(const uint32_t*)(smc + ((r0+8)*ST + cb + 8)*2);
            al[i][0] = *(const uint32_t*)(smc + OFF_ALO + (r0*ST + cb)*2);
            al[i][1] = *(const uint32_t*)(smc + OFF_ALO + ((r0+8)*ST + cb)*2);
            al[i][2] = *(const uint32_t*)(smc + OFF_ALO + (r0*ST + cb + 8)*2);
            al[i][3] = *(const uint32_t*)(smc + OFF_ALO + ((r0+8)*ST + cb + 8)*2);
        }
#pragma unroll
        for (int j = 0; j < 8; j++) {
            int ro = wo*64 + j*8 + g;
            uint32_t bh0 = *(const uint32_t*)(smc + OFF_WHI + (ro*ST + cb)*2);
            uint32_t bh1 = *(const uint32_t*)(smc + OFF_WHI + (ro*ST + cb + 8)*2);
#pragma unroll
            for (int i = 0; i < 4; i++) {
                mma16816h(acc[i][j], ah[i][0], ah[i][1], ah[i][2], ah[i][3], bh0, bh1);
                mma16816h(acc[i][j], al[i][0], al[i][1], al[i][2], al[i][3], bh0, bh1);
            }
        }
    }
}

template<int LAYER>
__global__ void __launch_bounds__(256, 1) gemm_kernel() {
    const __half* Wh = LAYER ? d_W2h : d_W1h;
    const int KT  = LAYER ? KT2 : KT1;
    const int nKB = KT >> 5;

    extern __shared__ char sm[];
    int tid = threadIdx.x, lane = tid & 31, wid = tid >> 5;
    int g = lane >> 2, m = lane & 3;
    int wn = wid & 1, wo = wid >> 1;
    int nbase = blockIdx.x * 128;

    float* sA = (float*)(sm + SM_A1);
    float* sC = (float*)(sm + SM_C1);
    if (LAYER) { sA[tid] = d_aA[tid]; sC[tid] = d_cA[tid]; }

    float acc[4][8][4];
#pragma unroll
    for (int i = 0; i < 4; i++)
#pragma unroll
        for (int j = 0; j < 8; j++)
#pragma unroll
            for (int e = 0; e < 4; e++) acc[i][j][e] = 0.0f;

    float4 rg[4];
    // prologue: stage chunk 0 into buffer 0
    if (LAYER) {
        __syncthreads();            // sA/sC visible
        prefA1(rg, nbase, 0, tid);
        stageA1(sm, rg, 0, tid, sA, sC);
    } else {
        stageA0(sm, nbase, 0, tid);
    }
    stageW(sm, Wh, KT, 0, tid);
    CP_COMMIT();
    if (LAYER) prefA1(rg, nbase, 1, tid);

    // triple-buffered mainloop: ONE __syncthreads per chunk
    for (int kb = 0; kb < nKB; kb++) {
        char* cur = sm + (kb % 3) * BUFSZ;
        char* nxt = sm + ((kb + 1) % 3) * BUFSZ;
        if (kb + 1 < nKB) {
            if (LAYER) {
                stageA1(nxt, rg, kb + 1, tid, sA, sC);
                if (kb + 2 < nKB) prefA1(rg, nbase, kb + 2, tid);
            } else {
                stageA0(nxt, nbase, kb + 1, tid);
            }
            stageW(nxt, Wh, KT, kb + 1, tid);
            CP_COMMIT();
            CP_WAIT1();
        } else {
            CP_WAIT0();
        }
        __syncthreads();
        compute_chunk(cur, wn, wo, g, m, acc);
    }
    __syncthreads();

    // ---------------- epilogue -------------------------------------------------
    float* ys = (float*)(sm + SM_YS);
    float* qs = (float*)(sm + SM_QS);
    ys[tid] = 0.0f; qs[tid] = 0.0f;
    __syncthreads();

    float sc[8][2], qc[8][2];
#pragma unroll
    for (int j = 0; j < 8; j++) { sc[j][0]=sc[j][1]=qc[j][0]=qc[j][1]=0.0f; }

#pragma unroll
    for (int i = 0; i < 4; i++) {
        int r0 = nbase + wn*64 + i*16 + g;
#pragma unroll
        for (int j = 0; j < 8; j++) {
            int col = wo*64 + j*8 + 2*m;
            float v0 = acc[i][j][0], v1 = acc[i][j][1];
            float v2 = acc[i][j][2], v3 = acc[i][j][3];
            if (!LAYER) {
                *(float2*)(d_Y1 + (size_t)r0*256 + col)     = make_float2(v0, v1);
                *(float2*)(d_Y1 + (size_t)(r0+8)*256 + col) = make_float2(v2, v3);
            } else {
                // per-query max/min over k (query = 16 consecutive tokens)
                float mxa = fmaxf(v0, v2), mxb = fmaxf(v1, v3);
                float mna = fminf(v0, v2), mnb = fminf(v1, v3);
#pragma unroll
                for (int off = 4; off < 32; off <<= 1) {
                    mxa = fmaxf(mxa, __shfl_xor_sync(0xFFFFFFFFu, mxa, off));
                    mxb = fmaxf(mxb, __shfl_xor_sync(0xFFFFFFFFu, mxb, off));
                    mna = fminf(mna, __shfl_xor_sync(0xFFFFFFFFu, mna, off));
                    mnb = fminf(mnb, __shfl_xor_sync(0xFFFFFFFFu, mnb, off));
                }
                if (g == 0) {
                    int q = blockIdx.x*8 + wn*4 + i;
                    *(float2*)(d_qmax + (size_t)q*256 + col) = make_float2(mxa, mxb);
                    *(float2*)(d_qmin + (size_t)q*256 + col) = make_float2(mna, mnb);
                }
            }
            sc[j][0] += v0 + v2;       sc[j][1] += v1 + v3;
            qc[j][0] += v0*v0 + v2*v2; qc[j][1] += v1*v1 + v3*v3;
        }
    }
#pragma unroll
    for (int j = 0; j < 8; j++)
#pragma unroll
        for (int e = 0; e < 2; e++) {
#pragma unroll
            for (int off = 4; off < 32; off <<= 1) {
                sc[j][e] += __shfl_xor_sync(0xFFFFFFFFu, sc[j][e], off);
                qc[j][e] += __shfl_xor_sync(0xFFFFFFFFu, qc[j][e], off);
            }
        }
    if (wn == 0 && lane < 4) {
#pragma unroll
        for (int j = 0; j < 8; j++) {
            int col = wo*64 + j*8 + 2*lane;
            ys[col] = sc[j][0];   ys[col+1] = sc[j][1];
            qs[col] = qc[j][0];   qs[col+1] = qc[j][1];
        }
    }
    __syncthreads();
    if (wn == 1 && lane < 4) {
#pragma unroll
        for (int j = 0; j < 8; j++) {
            int col = wo*64 + j*8 + 2*lane;
            ys[col] += sc[j][0];  ys[col+1] += sc[j][1];
            qs[col] += qc[j][0];  qs[col+1] += qc[j][1];
        }
    }
    __syncthreads();
    d_psY[(size_t)tid*NTILES + blockIdx.x] = ys[tid];
    d_psQ[(size_t)tid*NTILES + blockIdx.x] = qs[tid];
}

// ---------------- BN stats finalize (256 blocks, coalesced) --------------------
__global__ void __launch_bounds__(256) stats_final(int layer,
                                                   const float* __restrict__ g,
                                                   const float* __restrict__ bt) {
    int o = blockIdx.x, t = threadIdx.x;
    float s = 0.0f, q = 0.0f;
    for (int i = t; i < NTILES; i += 256) {
        s += d_psY[(size_t)o*NTILES + i];
        q += d_psQ[(size_t)o*NTILES + i];
    }
    __shared__ float ss[8], sq[8];
#pragma unroll
    for (int off = 16; off > 0; off >>= 1) {
        s += __shfl_down_sync(0xFFFFFFFFu, s, off);
        q += __shfl_down_sync(0xFFFFFFFFu, q, off);
    }
    if ((t & 31) == 0) { ss[t >> 5] = s; sq[t >> 5] = q; }
    __syncthreads();
    if (t == 0) {
        float S = 0.0f, Q = 0.0f;
#pragma unroll
        for (int i = 0; i < 8; i++) { S += ss[i]; Q += sq[i]; }
        float mean = S * (1.0f / NT);
        float var  = Q * (1.0f / NT) - mean*mean;
        float av = rsqrtf(var + 1e-5f) * g[o];
        d_aA[layer*256 + o] = av;
        d_cA[layer*256 + o] = bt[o] - mean * av;   // bias-free (cancels in BN)
    }
}

// ----------- final: pick max/min by sign(a2), affine + relu --------------------
__global__ void __launch_bounds__(256) final_kernel(float* __restrict__ out) {
    size_t idx = (size_t)blockIdx.x * 256 + threadIdx.x;
    int o = threadIdx.x;
    float a = d_aA[256 + o], c = d_cA[256 + o];
    float v = (a >= 0.0f) ? d_qmax[idx] : d_qmin[idx];
    out[OUT_XYZ + idx] = fmaxf(fmaf(v, a, c), 0.0f);
}

// ------------------------------- launch ----------------------------------------
extern "C" void kernel_launch(void* const* d_in, const int* in_sizes, int n_in,
                              void* d_out, int out_size) {
    const float* xyz    = (const float*)d_in[0];
    const float* points = (const float*)d_in[1];
    const float* W1  = (const float*)d_in[2];
    const float* g1  = (const float*)d_in[4];
    const float* bt1 = (const float*)d_in[5];
    const float* W2  = (const float*)d_in[6];
    const float* g2  = (const float*)d_in[8];
    const float* bt2 = (const float*)d_in[9];
    float* out = (float*)d_out;

    cudaFuncSetAttribute(gemm_kernel<0>, cudaFuncAttributeMaxDynamicSharedMemorySize, SM_TOT);
    cudaFuncSetAttribute(gemm_kernel<1>, cudaFuncAttributeMaxDynamicSharedMemorySize, SM_TOT);

    // keep knng as the 4th launch so ncu captures it (verify revert)
    prep1_kernel<<<192, 256>>>(W1);
    prep2_kernel<<<256, 256>>>(W2);
    fps_kernel<<<Bq, 512>>>(xyz, out);
    knng_kernel<<<dim3(Sq, Bq), 256>>>(xyz, points);
    gemm_kernel<0><<<NTILES, 256, SM_TOT>>>();
    stats_final<<<256, 256>>>(0, g1, bt1);
    gemm_kernel<1><<<NTILES, 256, SM_TOT>>>();
    stats_final<<<256, 256>>>(1, g2, bt2);
    final_kernel<<<Bq*Sq, 256>>>(out);
}

// round 14
// speedup vs baseline: 1.2171x; 1.0555x over previous
#include <cuda_runtime.h>
#include <cuda_fp16.h>
#include <math_constants.h>
#include <cstdint>

// Problem constants
#define Bq   16
#define Nq   4096
#define Dq   128
#define Sq   1024
#define Kq   16
#define CIN  131            // 3 + D
#define KT1  192            // layer-1 K padded (6 chunks of 32)
#define KT2  256            // layer-2 K (8 chunks of 32)
#define NT   (Bq*Sq*Kq)     // 262144 tokens
#define NTILES (NT/128)     // 2048 n-tiles
#define OUT_XYZ (Bq*Sq*3)

// ---------------- static device scratch -------------------------------------
__device__ float d_newxyz[Bq*Sq*3];
__device__ __align__(16) __half d_W1h[256*KT1];              // W hi plane only
__device__ __align__(16) __half d_W2h[256*KT2];
__device__ __align__(16) __half d_Fh[(size_t)NT*KT1], d_Fl[(size_t)NT*KT1];
__device__ __align__(16) float d_Y1[(size_t)NT*256];         // layer1 raw acc [n][o]
__device__ __align__(16) float d_qmax[Bq*Sq*256], d_qmin[Bq*Sq*256];
__device__ float d_psY[256*NTILES], d_psQ[256*NTILES];       // transposed partials
__device__ float d_aA[2*256], d_cA[2*256];

// ---------------- helpers ----------------------------------------------------
__device__ __forceinline__ float sqdist(float px, float py, float pz,
                                        float cx, float cy, float cz) {
    float dx = px - cx, dy = py - cy, dz = pz - cz;
    return __fadd_rn(__fadd_rn(__fmul_rn(dx, dx), __fmul_rn(dy, dy)),
                     __fmul_rn(dz, dz));
}

__device__ __forceinline__ void split2h(float v, __half& h, __half& l) {
    h = __float2half_rn(v);
    l = __float2half_rn(v - __half2float(h));
}

__device__ __forceinline__ unsigned long long umax64(unsigned long long a,
                                                     unsigned long long b) {
    return a > b ? a : b;
}

__device__ __forceinline__ void mma16816h(float d[4], uint32_t a0, uint32_t a1,
                                          uint32_t a2, uint32_t a3,
                                          uint32_t b0, uint32_t b1) {
    asm volatile(
        "mma.sync.aligned.m16n8k16.row.col.f32.f16.f16.f32 "
        "{%0,%1,%2,%3}, {%4,%5,%6,%7}, {%8,%9}, {%0,%1,%2,%3};"
        : "+f"(d[0]), "+f"(d[1]), "+f"(d[2]), "+f"(d[3])
        : "r"(a0), "r"(a1), "r"(a2), "r"(a3), "r"(b0), "r"(b1));
}

#define CP16(dst, src) \
    asm volatile("cp.async.cg.shared.global [%0], [%1], 16;" :: "r"(dst), "l"(src) : "memory")
#define CP_COMMIT() asm volatile("cp.async.commit_group;" ::: "memory")
#define CP_WAIT1()  asm volatile("cp.async.wait_group 1;" ::: "memory")
#define CP_WAIT0()  asm volatile("cp.async.wait_group 0;" ::: "memory")

// ------------- FPS (R13 structure; warp reduce -> two u32 redux ops) -----------
__global__ void __launch_bounds__(512) fps_kernel(const float* __restrict__ xyz,
                                                  float* __restrict__ out) {
    int b = blockIdx.x, t = threadIdx.x;
    const float* base = xyz + (size_t)b * Nq * 3;
    float px[8], py[8], pz[8], dist[8];
#pragma unroll
    for (int i = 0; i < 8; i++) {
        int n = i * 512 + t;
        px[i] = base[n*3+0]; py[i] = base[n*3+1]; pz[i] = base[n*3+2];
        dist[i] = 1e10f;
    }
    __shared__ unsigned long long wred[2][16];
    int lane = t & 31, w = t >> 5;
    int far = 0;
    for (int it = 0; it < Sq; it++) {
        float cx = __ldg(base + far*3 + 0);
        float cy = __ldg(base + far*3 + 1);
        float cz = __ldg(base + far*3 + 2);
        if (t == 0) {
            int o = (b*Sq + it) * 3;
            d_newxyz[o] = cx; d_newxyz[o+1] = cy; d_newxyz[o+2] = cz;
            out[o] = cx; out[o+1] = cy; out[o+2] = cz;
        }
        unsigned long long best = 0ULL;
#pragma unroll
        for (int i = 0; i < 8; i++) {
            float d  = sqdist(px[i], py[i], pz[i], cx, cy, cz);
            float dd = fminf(dist[i], d);
            dist[i]  = dd;
            unsigned long long key =
                ((unsigned long long)__float_as_uint(dd) << 32) |
                (unsigned)~(unsigned)(i*512 + t);
            if (key > best) best = key;
        }
        // warp lexicographic max via two u32 redux ops (ISOLATED change vs R13)
        unsigned bd = (unsigned)(best >> 32);
        unsigned bn = (unsigned)best;
        unsigned wd = __reduce_max_sync(0xFFFFFFFFu, bd);
        unsigned cn = (bd == wd) ? bn : 0u;     // bn = ~idx >= 0xFFFFE000, never 0
        unsigned wl = __reduce_max_sync(0xFFFFFFFFu, cn);
        if (lane == 0)
            wred[it & 1][w] = ((unsigned long long)wd << 32) | wl;
        __syncthreads();
        const unsigned long long* wr = wred[it & 1];
        unsigned long long t0 = umax64(wr[0],  wr[1]);
        unsigned long long t1 = umax64(wr[2],  wr[3]);
        unsigned long long t2 = umax64(wr[4],  wr[5]);
        unsigned long long t3 = umax64(wr[6],  wr[7]);
        unsigned long long t4 = umax64(wr[8],  wr[9]);
        unsigned long long t5 = umax64(wr[10], wr[11]);
        unsigned long long t6 = umax64(wr[12], wr[13]);
        unsigned long long t7 = umax64(wr[14], wr[15]);
        unsigned long long s0 = umax64(umax64(t0, t1), umax64(t2, t3));
        unsigned long long s1 = umax64(umax64(t4, t5), umax64(t6, t7));
        far = (int)(~(unsigned)umax64(s0, s1));
    }
}

// ---- fused kNN + gather + fp16-split (R13 version, verbatim) ------------------
__global__ void __launch_bounds__(256) knng_kernel(const float* __restrict__ xyz,
                                                   const float* __restrict__ points) {
    int s = blockIdx.x, b = blockIdx.y, t = threadIdx.x;
    const float* base = xyz + (size_t)b * Nq * 3;
    int qo = b*Sq + s;
    float cx = d_newxyz[qo*3], cy = d_newxyz[qo*3+1], cz = d_newxyz[qo*3+2];

    __shared__ float ds[Nq];
    __shared__ unsigned long long wred[8];
    __shared__ unsigned long long winner;
    __shared__ int idx[Kq];

    unsigned bd = 0xFFFFFFFFu, bi = 0u;
#pragma unroll 4
    for (int j = 0; j < 16; j++) {
        int n = j*256 + t;
        float d = sqdist(base[n*3], base[n*3+1], base[n*3+2], cx, cy, cz);
        ds[n] = d;
        unsigned ud = __float_as_uint(d);
        if (ud < bd) { bd = ud; bi = (unsigned)n; }
    }
    int lane = t & 31, w = t >> 5;
    for (int r = 0; r < Kq; r++) {
        unsigned wd = __reduce_min_sync(0xFFFFFFFFu, bd);
        unsigned ci = (bd == wd) ? bi : 0xFFFFFFFFu;
        unsigned wi = __reduce_min_sync(0xFFFFFFFFu, ci);
        if (lane == 0) wred[w] = ((unsigned long long)wd << 32) | wi;
        __syncthreads();
        if (t == 0) {
            unsigned long long m = wred[0];
#pragma unroll
            for (int i = 1; i < 8; i++) if (wred[i] < m) m = wred[i];
            winner = m;
            idx[r] = (int)(unsigned)m;
        }
        __syncthreads();
        if (r < Kq-1) {
            unsigned widx = (unsigned)winner;
            if ((widx & 255u) == (unsigned)t) {
                ds[widx] = CUDART_INF_F;
                bd = 0xFFFFFFFFu; bi = 0u;
#pragma unroll 4
                for (int j = 0; j < 16; j++) {
                    int n = j*256 + t;
                    unsigned ud = __float_as_uint(ds[n]);
                    if (ud < bd) { bd = ud; bi = (unsigned)n; }
                }
            }
        }
    }
    __syncthreads();
    // gather + split
    const float* pbase = points + (size_t)b * Nq * Dq;
    size_t rowb = (size_t)qo * Kq * KT1;
    for (int e = t; e < Kq*KT1; e += 256) {
        int k = e / KT1, c = e - k*KT1;
        int n = idx[k];
        float v = 0.0f;
        if (c < 3) v = base[n*3 + c] - ((c == 0) ? cx : ((c == 1) ? cy : cz));
        else if (c < CIN) v = pbase[(size_t)n*Dq + (c-3)];
        __half h, l; split2h(v, h, l);
        d_Fh[rowb + e] = h; d_Fl[rowb + e] = l;
    }
}

// ------------------- weight fp16 (hi only) + pad; prep1 split -------------------
__global__ void prep1a_kernel(const float* __restrict__ W1) {
    int i = blockIdx.x * 256 + threadIdx.x;      // o in [0,128)
    if (i < 128*KT1) {
        int o = i / KT1, c = i - o*KT1;
        d_W1h[i] = __float2half_rn((c < CIN) ? W1[o*CIN + c] : 0.0f);
    }
}

__global__ void prep1b_kernel(const float* __restrict__ W1) {
    int i = blockIdx.x * 256 + threadIdx.x;      // o in [128,256)
    if (i < 128*KT1) {
        int o = 128 + i / KT1, c = i - (i / KT1)*KT1;
        d_W1h[(size_t)o*KT1 + c] = __float2half_rn((c < CIN) ? W1[o*CIN + c] : 0.0f);
    }
}

__global__ void prep2_kernel(const float* __restrict__ W2) {
    int i = blockIdx.x * 256 + threadIdx.x;
    if (i < 256*KT2) {
        int o = i >> 8, c = i & 255;
        d_W2h[i] = __float2half_rn(W2[o*256 + c]);
    }
}

// ---------- pipelined HMMA fp16 2-MMA GEMM (triple buffer, 1 sync) -------------
#define ST  40
#define APL (128*ST*2)            // 10240 B per A plane
#define WPL (256*ST*2)            // 20480 B for W hi plane
#define OFF_ALO APL
#define OFF_WHI (2*APL)
#define BUFSZ   (2*APL + WPL)     // 40960
#define SM_YS   (3*BUFSZ)
#define SM_QS   (SM_YS + 1024)
#define SM_A1   (SM_QS + 1024)
#define SM_C1   (SM_A1 + 1024)
#define SM_TOT  (SM_C1 + 1024)    // 126976

__device__ __forceinline__ void stageW(char* dst, const __half* __restrict__ Wh,
                                       int KT, int kb, int tid) {
#pragma unroll
    for (int it = 0; it < 4; it++) {
        int u = tid + it*256, o = u >> 2, q = u & 3;
        size_t go = (size_t)o*KT + kb*32 + q*8;
        uint32_t sh = (uint32_t)__cvta_generic_to_shared(dst + OFF_WHI + (o*ST + q*8)*2);
        CP16(sh, Wh + go);
    }
}

__device__ __forceinline__ void stageA0(char* dst, int nbase, int kb, int tid) {
#pragma unroll
    for (int it = 0; it < 2; it++) {
        int u = tid + it*256, r = u >> 2, q = u & 3;
        size_t go = (size_t)(nbase + r)*KT1 + kb*32 + q*8;
        uint32_t sh = (uint32_t)__cvta_generic_to_shared(dst + (r*ST + q*8)*2);
        uint32_t sl = (uint32_t)__cvta_generic_to_shared(dst + OFF_ALO + (r*ST + q*8)*2);
        CP16(sh, d_Fh + go);
        CP16(sl, d_Fl + go);
    }
}

__device__ __forceinline__ void prefA1(float4 rg[4], int nbase, int kb, int tid) {
#pragma unroll
    for (int it = 0; it < 2; it++) {
        int u = tid + it*256, r = u >> 2, q = u & 3;
        const float* src = d_Y1 + (size_t)(nbase + r)*256 + kb*32 + q*8;
        rg[it*2]   = *(const float4*)src;
        rg[it*2+1] = *(const float4*)(src + 4);
    }
}

__device__ __forceinline__ void stageA1(char* dst, const float4 rg[4], int kb,
                                        int tid, const float* sA, const float* sC) {
#pragma unroll
    for (int it = 0; it < 2; it++) {
        int u = tid + it*256, r = u >> 2, q = u & 3;
        int cb = kb*32 + q*8;
        float vs[8] = {rg[it*2].x, rg[it*2].y, rg[it*2].z, rg[it*2].w,
                       rg[it*2+1].x, rg[it*2+1].y, rg[it*2+1].z, rg[it*2+1].w};
        uint32_t hp[4], lp[4];
#pragma unroll
        for (int jp = 0; jp < 4; jp++) {
            float v0 = fmaxf(fmaf(vs[2*jp],   sA[cb+2*jp],   sC[cb+2*jp]),   0.0f);
            float v1 = fmaxf(fmaf(vs[2*jp+1], sA[cb+2*jp+1], sC[cb+2*jp+1]), 0.0f);
            __half h0, l0, h1, l1;
            split2h(v0, h0, l0); split2h(v1, h1, l1);
            hp[jp] = (uint32_t)__half_as_ushort(h0) |
                     ((uint32_t)__half_as_ushort(h1) << 16);
            lp[jp] = (uint32_t)__half_as_ushort(l0) |
                     ((uint32_t)__half_as_ushort(l1) << 16);
        }
        *(uint4*)(dst + (r*ST + q*8)*2)           = make_uint4(hp[0], hp[1], hp[2], hp[3]);
        *(uint4*)(dst + OFF_ALO + (r*ST + q*8)*2) = make_uint4(lp[0], lp[1], lp[2], lp[3]);
    }
}

__device__ __forceinline__ void compute_chunk(const char* smc, int wn, int wo,
                                              int g, int m, float acc[4][8][4]) {
#pragma unroll
    for (int ks = 0; ks < 2; ks++) {
        int cb = ks*16 + 2*m;
        uint32_t ah[4][4], al[4][4];
#pragma unroll
        for (int i = 0; i < 4; i++) {
            int r0 = wn*64 + i*16 + g;
            ah[i][0] = *(const uint32_t*)(smc + (r0*ST + cb)*2);
            ah[i][1] = *(const uint32_t*)(smc + ((r0+8)*ST + cb)*2);
            ah[i][2] = *(const uint32_t*)(smc + (r0*ST + cb + 8)*2);
            ah[i][3] = *(const uint32_t*)(smc + ((r0+8)*ST + cb + 8)*2);
            al[i][0] = *(const uint32_t*)(smc + OFF_ALO + (r0*ST + cb)*2);
            al[i][1] = *(const uint32_t*)(smc + OFF_ALO + ((r0+8)*ST + cb)*2);
            al[i][2] = *(const uint32_t*)(smc + OFF_ALO + (r0*ST + cb + 8)*2);
            al[i][3] = *(const uint32_t*)(smc + OFF_ALO + ((r0+8)*ST + cb + 8)*2);
        }
#pragma unroll
        for (int j = 0; j < 8; j++) {
            int ro = wo*64 + j*8 + g;
            uint32_t bh0 = *(const uint32_t*)(smc + OFF_WHI + (ro*ST + cb)*2);
            uint32_t bh1 = *(const uint32_t*)(smc + OFF_WHI + (ro*ST + cb + 8)*2);
#pragma unroll
            for (int i = 0; i < 4; i++) {
                mma16816h(acc[i][j], ah[i][0], ah[i][1], ah[i][2], ah[i][3], bh0, bh1);
                mma16816h(acc[i][j], al[i][0], al[i][1], al[i][2], al[i][3], bh0, bh1);
            }
        }
    }
}

template<int LAYER>
__global__ void __launch_bounds__(256, 1) gemm_kernel() {
    const __half* Wh = LAYER ? d_W2h : d_W1h;
    const int KT  = LAYER ? KT2 : KT1;
    const int nKB = KT >> 5;

    extern __shared__ char sm[];
    int tid = threadIdx.x, lane = tid & 31, wid = tid >> 5;
    int g = lane >> 2, m = lane & 3;
    int wn = wid & 1, wo = wid >> 1;
    int nbase = blockIdx.x * 128;

    float* sA = (float*)(sm + SM_A1);
    float* sC = (float*)(sm + SM_C1);
    if (LAYER) { sA[tid] = d_aA[tid]; sC[tid] = d_cA[tid]; }

    float acc[4][8][4];
#pragma unroll
    for (int i = 0; i < 4; i++)
#pragma unroll
        for (int j = 0; j < 8; j++)
#pragma unroll
            for (int e = 0; e < 4; e++) acc[i][j][e] = 0.0f;

    float4 rg[4];
    if (LAYER) {
        __syncthreads();
        prefA1(rg, nbase, 0, tid);
        stageA1(sm, rg, 0, tid, sA, sC);
    } else {
        stageA0(sm, nbase, 0, tid);
    }
    stageW(sm, Wh, KT, 0, tid);
    CP_COMMIT();
    if (LAYER) prefA1(rg, nbase, 1, tid);

    for (int kb = 0; kb < nKB; kb++) {
        char* cur = sm + (kb % 3) * BUFSZ;
        char* nxt = sm + ((kb + 1) % 3) * BUFSZ;
        if (kb + 1 < nKB) {
            if (LAYER) {
                stageA1(nxt, rg, kb + 1, tid, sA, sC);
                if (kb + 2 < nKB) prefA1(rg, nbase, kb + 2, tid);
            } else {
                stageA0(nxt, nbase, kb + 1, tid);
            }
            stageW(nxt, Wh, KT, kb + 1, tid);
            CP_COMMIT();
            CP_WAIT1();
        } else {
            CP_WAIT0();
        }
        __syncthreads();
        compute_chunk(cur, wn, wo, g, m, acc);
    }
    __syncthreads();

    // ---------------- epilogue -------------------------------------------------
    float* ys = (float*)(sm + SM_YS);
    float* qs = (float*)(sm + SM_QS);
    ys[tid] = 0.0f; qs[tid] = 0.0f;
    __syncthreads();

    float sc[8][2], qc[8][2];
#pragma unroll
    for (int j = 0; j < 8; j++) { sc[j][0]=sc[j][1]=qc[j][0]=qc[j][1]=0.0f; }

#pragma unroll
    for (int i = 0; i < 4; i++) {
        int r0 = nbase + wn*64 + i*16 + g;
#pragma unroll
        for (int j = 0; j < 8; j++) {
            int col = wo*64 + j*8 + 2*m;
            float v0 = acc[i][j][0], v1 = acc[i][j][1];
            float v2 = acc[i][j][2], v3 = acc[i][j][3];
            if (!LAYER) {
                *(float2*)(d_Y1 + (size_t)r0*256 + col)     = make_float2(v0, v1);
                *(float2*)(d_Y1 + (size_t)(r0+8)*256 + col) = make_float2(v2, v3);
            } else {
                float mxa = fmaxf(v0, v2), mxb = fmaxf(v1, v3);
                float mna = fminf(v0, v2), mnb = fminf(v1, v3);
#pragma unroll
                for (int off = 4; off < 32; off <<= 1) {
                    mxa = fmaxf(mxa, __shfl_xor_sync(0xFFFFFFFFu, mxa, off));
                    mxb = fmaxf(mxb, __shfl_xor_sync(0xFFFFFFFFu, mxb, off));
                    mna = fminf(mna, __shfl_xor_sync(0xFFFFFFFFu, mna, off));
                    mnb = fminf(mnb, __shfl_xor_sync(0xFFFFFFFFu, mnb, off));
                }
                if (g == 0) {
                    int q = blockIdx.x*8 + wn*4 + i;
                    *(float2*)(d_qmax + (size_t)q*256 + col) = make_float2(mxa, mxb);
                    *(float2*)(d_qmin + (size_t)q*256 + col) = make_float2(mna, mnb);
                }
            }
            sc[j][0] += v0 + v2;       sc[j][1] += v1 + v3;
            qc[j][0] += v0*v0 + v2*v2; qc[j][1] += v1*v1 + v3*v3;
        }
    }
#pragma unroll
    for (int j = 0; j < 8; j++)
#pragma unroll
        for (int e = 0; e < 2; e++) {
#pragma unroll
            for (int off = 4; off < 32; off <<= 1) {
                sc[j][e] += __shfl_xor_sync(0xFFFFFFFFu, sc[j][e], off);
                qc[j][e] += __shfl_xor_sync(0xFFFFFFFFu, qc[j][e], off);
            }
        }
    if (wn == 0 && lane < 4) {
#pragma unroll
        for (int j = 0; j < 8; j++) {
            int col = wo*64 + j*8 + 2*lane;
            ys[col] = sc[j][0];   ys[col+1] = sc[j][1];
            qs[col] = qc[j][0];   qs[col+1] = qc[j][1];
        }
    }
    __syncthreads();
    if (wn == 1 && lane < 4) {
#pragma unroll
        for (int j = 0; j < 8; j++) {
            int col = wo*64 + j*8 + 2*lane;
            ys[col] += sc[j][0];  ys[col+1] += sc[j][1];
            qs[col] += qc[j][0];  qs[col+1] += qc[j][1];
        }
    }
    __syncthreads();
    d_psY[(size_t)tid*NTILES + blockIdx.x] = ys[tid];
    d_psQ[(size_t)tid*NTILES + blockIdx.x] = qs[tid];
}

// ---------------- BN stats finalize (256 blocks, coalesced) --------------------
__global__ void __launch_bounds__(256) stats_final(int layer,
                                                   const float* __restrict__ g,
                                                   const float* __restrict__ bt) {
    int o = blockIdx.x, t = threadIdx.x;
    float s = 0.0f, q = 0.0f;
    for (int i = t; i < NTILES; i += 256) {
        s += d_psY[(size_t)o*NTILES + i];
        q += d_psQ[(size_t)o*NTILES + i];
    }
    __shared__ float ss[8], sq[8];
#pragma unroll
    for (int off = 16; off > 0; off >>= 1) {
        s += __shfl_down_sync(0xFFFFFFFFu, s, off);
        q += __shfl_down_sync(0xFFFFFFFFu, q, off);
    }
    if ((t & 31) == 0) { ss[t >> 5] = s; sq[t >> 5] = q; }
    __syncthreads();
    if (t == 0) {
        float S = 0.0f, Q = 0.0f;
#pragma unroll
        for (int i = 0; i < 8; i++) { S += ss[i]; Q += sq[i]; }
        float mean = S * (1.0f / NT);
        float var  = Q * (1.0f / NT) - mean*mean;
        float av = rsqrtf(var + 1e-5f) * g[o];
        d_aA[layer*256 + o] = av;
        d_cA[layer*256 + o] = bt[o] - mean * av;   // bias-free (cancels in BN)
    }
}

// ----------- final: pick max/min by sign(a2), affine + relu --------------------
__global__ void __launch_bounds__(256) final_kernel(float* __restrict__ out) {
    size_t idx = (size_t)blockIdx.x * 256 + threadIdx.x;
    int o = threadIdx.x;
    float a = d_aA[256 + o], c = d_cA[256 + o];
    float v = (a >= 0.0f) ? d_qmax[idx] : d_qmin[idx];
    out[OUT_XYZ + idx] = fmaxf(fmaf(v, a, c), 0.0f);
}

// ------------------------------- launch ----------------------------------------
extern "C" void kernel_launch(void* const* d_in, const int* in_sizes, int n_in,
                              void* d_out, int out_size) {
    const float* xyz    = (const float*)d_in[0];
    const float* points = (const float*)d_in[1];
    const float* W1  = (const float*)d_in[2];
    const float* g1  = (const float*)d_in[4];
    const float* bt1 = (const float*)d_in[5];
    const float* W2  = (const float*)d_in[6];
    const float* g2  = (const float*)d_in[8];
    const float* bt2 = (const float*)d_in[9];
    float* out = (float*)d_out;

    cudaFuncSetAttribute(gemm_kernel<0>, cudaFuncAttributeMaxDynamicSharedMemorySize, SM_TOT);
    cudaFuncSetAttribute(gemm_kernel<1>, cudaFuncAttributeMaxDynamicSharedMemorySize, SM_TOT);

    // fps is now the 4th launch -> ncu captures it (first direct FPS profile)
    prep1a_kernel<<<96, 256>>>(W1);
    prep1b_kernel<<<96, 256>>>(W1);
    prep2_kernel<<<256, 256>>>(W2);
    fps_kernel<<<Bq, 512>>>(xyz, out);
    knng_kernel<<<dim3(Sq, Bq), 256>>>(xyz, points);
    gemm_kernel<0><<<NTILES, 256, SM_TOT>>>();
    stats_final<<<256, 256>>>(0, g1, bt1);
    gemm_kernel<1><<<NTILES, 256, SM_TOT>>>();
    stats_final<<<256, 256>>>(1, g2, bt2);
    final_kernel<<<Bq*Sq, 256>>>(out);
}

// round 15
// speedup vs baseline: 1.4944x; 1.2279x over previous
#include <cuda_runtime.h>
#include <cuda_fp16.h>
#include <math_constants.h>
#include <cstdint>

// Problem constants
#define Bq   16
#define Nq   4096
#define Dq   128
#define Sq   1024
#define Kq   16
#define CIN  131            // 3 + D
#define KT1  192            // layer-1 K padded (6 chunks of 32)
#define KT2  256            // layer-2 K (8 chunks of 32)
#define NT   (Bq*Sq*Kq)     // 262144 tokens
#define NTILES (NT/128)     // 2048 n-tiles
#define OUT_XYZ (Bq*Sq*3)

// ---------------- static device scratch -------------------------------------
__device__ float d_newxyz[Bq*Sq*3];
__device__ __align__(16) __half d_W1h[256*KT1];              // W hi plane only
__device__ __align__(16) __half d_W2h[256*KT2];
__device__ __align__(16) __half d_Fh[(size_t)NT*KT1], d_Fl[(size_t)NT*KT1];
__device__ __align__(16) float d_Y1[(size_t)NT*256];         // layer1 raw acc [n][o]
__device__ __align__(16) float d_qmax[Bq*Sq*256], d_qmin[Bq*Sq*256];
__device__ float d_psY[256*NTILES], d_psQ[256*NTILES];       // transposed partials
__device__ float d_aA[2*256], d_cA[2*256];

// ---------------- helpers ----------------------------------------------------
__device__ __forceinline__ float sqdist(float px, float py, float pz,
                                        float cx, float cy, float cz) {
    float dx = px - cx, dy = py - cy, dz = pz - cz;
    return __fadd_rn(__fadd_rn(__fmul_rn(dx, dx), __fmul_rn(dy, dy)),
                     __fmul_rn(dz, dz));
}

__device__ __forceinline__ void split2h(float v, __half& h, __half& l) {
    h = __float2half_rn(v);
    l = __float2half_rn(v - __half2float(h));
}

__device__ __forceinline__ void mma16816h(float d[4], uint32_t a0, uint32_t a1,
                                          uint32_t a2, uint32_t a3,
                                          uint32_t b0, uint32_t b1) {
    asm volatile(
        "mma.sync.aligned.m16n8k16.row.col.f32.f16.f16.f32 "
        "{%0,%1,%2,%3}, {%4,%5,%6,%7}, {%8,%9}, {%0,%1,%2,%3};"
        : "+f"(d[0]), "+f"(d[1]), "+f"(d[2]), "+f"(d[3])
        : "r"(a0), "r"(a1), "r"(a2), "r"(a3), "r"(b0), "r"(b1));
}

#define CP16(dst, src) \
    asm volatile("cp.async.cg.shared.global [%0], [%1], 16;" :: "r"(dst), "l"(src) : "memory")
#define CP_COMMIT() asm volatile("cp.async.commit_group;" ::: "memory")
#define CP_WAIT1()  asm volatile("cp.async.wait_group 1;" ::: "memory")
#define CP_WAIT0()  asm volatile("cp.async.wait_group 0;" ::: "memory")

// ------ FPS: redux warp-reduce + warp-level final merge (no tree scan) ---------
__global__ void __launch_bounds__(512) fps_kernel(const float* __restrict__ xyz,
                                                  float* __restrict__ out) {
    int b = blockIdx.x, t = threadIdx.x;
    const float* base = xyz + (size_t)b * Nq * 3;
    float px[8], py[8], pz[8], dist[8];
#pragma unroll
    for (int i = 0; i < 8; i++) {
        int n = i * 512 + t;
        px[i] = base[n*3+0]; py[i] = base[n*3+1]; pz[i] = base[n*3+2];
        dist[i] = 1e10f;
    }
    __shared__ unsigned long long wred[2][16];
    int lane = t & 31, w = t >> 5;
    int far = 0;
    for (int it = 0; it < Sq; it++) {
        float cx = __ldg(base + far*3 + 0);
        float cy = __ldg(base + far*3 + 1);
        float cz = __ldg(base + far*3 + 2);
        if (t == 0) {
            int o = (b*Sq + it) * 3;
            d_newxyz[o] = cx; d_newxyz[o+1] = cy; d_newxyz[o+2] = cz;
            out[o] = cx; out[o+1] = cy; out[o+2] = cz;
        }
        unsigned long long best = 0ULL;
#pragma unroll
        for (int i = 0; i < 8; i++) {
            float d  = sqdist(px[i], py[i], pz[i], cx, cy, cz);
            float dd = fminf(dist[i], d);
            dist[i]  = dd;
            unsigned long long key =
                ((unsigned long long)__float_as_uint(dd) << 32) |
                (unsigned)~(unsigned)(i*512 + t);
            if (key > best) best = key;
        }
        // warp lexicographic max via two u32 redux ops
        unsigned bd = (unsigned)(best >> 32);
        unsigned bn = (unsigned)best;
        unsigned wd = __reduce_max_sync(0xFFFFFFFFu, bd);
        unsigned cn = (bd == wd) ? bn : 0u;     // bn = ~idx, never 0
        unsigned wl = __reduce_max_sync(0xFFFFFFFFu, cn);
        if (lane == 0)
            wred[it & 1][w] = ((unsigned long long)wd << 32) | wl;
        __syncthreads();
        // final merge over 16 warp winners, done warp-locally (8 instrs, no tree)
        unsigned long long v = wred[it & 1][lane & 15];
        unsigned hi = (unsigned)(v >> 32), lo = (unsigned)v;
        unsigned mh = __reduce_max_sync(0xFFFFFFFFu, hi);
        unsigned ml = __reduce_max_sync(0xFFFFFFFFu, (hi == mh) ? lo : 0u);
        far = (int)(~ml);
    }
}

// ---- fused kNN + gather + fp16-split (R13 version, verbatim) ------------------
__global__ void __launch_bounds__(256) knng_kernel(const float* __restrict__ xyz,
                                                   const float* __restrict__ points) {
    int s = blockIdx.x, b = blockIdx.y, t = threadIdx.x;
    const float* base = xyz + (size_t)b * Nq * 3;
    int qo = b*Sq + s;
    float cx = d_newxyz[qo*3], cy = d_newxyz[qo*3+1], cz = d_newxyz[qo*3+2];

    __shared__ float ds[Nq];
    __shared__ unsigned long long wred[8];
    __shared__ unsigned long long winner;
    __shared__ int idx[Kq];

    unsigned bd = 0xFFFFFFFFu, bi = 0u;
#pragma unroll 4
    for (int j = 0; j < 16; j++) {
        int n = j*256 + t;
        float d = sqdist(base[n*3], base[n*3+1], base[n*3+2], cx, cy, cz);
        ds[n] = d;
        unsigned ud = __float_as_uint(d);
        if (ud < bd) { bd = ud; bi = (unsigned)n; }
    }
    int lane = t & 31, w = t >> 5;
    for (int r = 0; r < Kq; r++) {
        unsigned wd = __reduce_min_sync(0xFFFFFFFFu, bd);
        unsigned ci = (bd == wd) ? bi : 0xFFFFFFFFu;
        unsigned wi = __reduce_min_sync(0xFFFFFFFFu, ci);
        if (lane == 0) wred[w] = ((unsigned long long)wd << 32) | wi;
        __syncthreads();
        if (t == 0) {
            unsigned long long m = wred[0];
#pragma unroll
            for (int i = 1; i < 8; i++) if (wred[i] < m) m = wred[i];
            winner = m;
            idx[r] = (int)(unsigned)m;
        }
        __syncthreads();
        if (r < Kq-1) {
            unsigned widx = (unsigned)winner;
            if ((widx & 255u) == (unsigned)t) {
                ds[widx] = CUDART_INF_F;
                bd = 0xFFFFFFFFu; bi = 0u;
#pragma unroll 4
                for (int j = 0; j < 16; j++) {
                    int n = j*256 + t;
                    unsigned ud = __float_as_uint(ds[n]);
                    if (ud < bd) { bd = ud; bi = (unsigned)n; }
                }
            }
        }
    }
    __syncthreads();
    // gather + split
    const float* pbase = points + (size_t)b * Nq * Dq;
    size_t rowb = (size_t)qo * Kq * KT1;
    for (int e = t; e < Kq*KT1; e += 256) {
        int k = e / KT1, c = e - k*KT1;
        int n = idx[k];
        float v = 0.0f;
        if (c < 3) v = base[n*3 + c] - ((c == 0) ? cx : ((c == 1) ? cy : cz));
        else if (c < CIN) v = pbase[(size_t)n*Dq + (c-3)];
        __half h, l; split2h(v, h, l);
        d_Fh[rowb + e] = h; d_Fl[rowb + e] = l;
    }
}

// ------------------- weight fp16 (hi only) + pad; prep1 split -------------------
__global__ void prep1a_kernel(const float* __restrict__ W1) {
    int i = blockIdx.x * 256 + threadIdx.x;      // o in [0,128)
    if (i < 128*KT1) {
        int o = i / KT1, c = i - o*KT1;
        d_W1h[i] = __float2half_rn((c < CIN) ? W1[o*CIN + c] : 0.0f);
    }
}

__global__ void prep1b_kernel(const float* __restrict__ W1) {
    int i = blockIdx.x * 256 + threadIdx.x;      // o in [128,256)
    if (i < 128*KT1) {
        int o = 128 + i / KT1, c = i - (i / KT1)*KT1;
        d_W1h[(size_t)o*KT1 + c] = __float2half_rn((c < CIN) ? W1[o*CIN + c] : 0.0f);
    }
}

__global__ void prep2_kernel(const float* __restrict__ W2) {
    int i = blockIdx.x * 256 + threadIdx.x;
    if (i < 256*KT2) {
        int o = i >> 8, c = i & 255;
        d_W2h[i] = __float2half_rn(W2[o*256 + c]);
    }
}

// ---------- pipelined HMMA fp16 2-MMA GEMM (triple buffer, 1 sync) -------------
#define ST  40
#define APL (128*ST*2)            // 10240 B per A plane
#define WPL (256*ST*2)            // 20480 B for W hi plane
#define OFF_ALO APL
#define OFF_WHI (2*APL)
#define BUFSZ   (2*APL + WPL)     // 40960
#define SM_YS   (3*BUFSZ)
#define SM_QS   (SM_YS + 1024)
#define SM_A1   (SM_QS + 1024)
#define SM_C1   (SM_A1 + 1024)
#define SM_TOT  (SM_C1 + 1024)    // 126976

__device__ __forceinline__ void stageW(char* dst, const __half* __restrict__ Wh,
                                       int KT, int kb, int tid) {
#pragma unroll
    for (int it = 0; it < 4; it++) {
        int u = tid + it*256, o = u >> 2, q = u & 3;
        size_t go = (size_t)o*KT + kb*32 + q*8;
        uint32_t sh = (uint32_t)__cvta_generic_to_shared(dst + OFF_WHI + (o*ST + q*8)*2);
        CP16(sh, Wh + go);
    }
}

__device__ __forceinline__ void stageA0(char* dst, int nbase, int kb, int tid) {
#pragma unroll
    for (int it = 0; it < 2; it++) {
        int u = tid + it*256, r = u >> 2, q = u & 3;
        size_t go = (size_t)(nbase + r)*KT1 + kb*32 + q*8;
        uint32_t sh = (uint32_t)__cvta_generic_to_shared(dst + (r*ST + q*8)*2);
        uint32_t sl = (uint32_t)__cvta_generic_to_shared(dst + OFF_ALO + (r*ST + q*8)*2);
        CP16(sh, d_Fh + go);
        CP16(sl, d_Fl + go);
    }
}

__device__ __forceinline__ void prefA1(float4 rg[4], int nbase, int kb, int tid) {
#pragma unroll
    for (int it = 0; it < 2; it++) {
        int u = tid + it*256, r = u >> 2, q = u & 3;
        const float* src = d_Y1 + (size_t)(nbase + r)*256 + kb*32 + q*8;
        rg[it*2]   = *(const float4*)src;
        rg[it*2+1] = *(const float4*)(src + 4);
    }
}

__device__ __forceinline__ void stageA1(char* dst, const float4 rg[4], int kb,
                                        int tid, const float* sA, const float* sC) {
#pragma unroll
    for (int it = 0; it < 2; it++) {
        int u = tid + it*256, r = u >> 2, q = u & 3;
        int cb = kb*32 + q*8;
        float vs[8] = {rg[it*2].x, rg[it*2].y, rg[it*2].z, rg[it*2].w,
                       rg[it*2+1].x, rg[it*2+1].y, rg[it*2+1].z, rg[it*2+1].w};
        uint32_t hp[4], lp[4];
#pragma unroll
        for (int jp = 0; jp < 4; jp++) {
            float v0 = fmaxf(fmaf(vs[2*jp],   sA[cb+2*jp],   sC[cb+2*jp]),   0.0f);
            float v1 = fmaxf(fmaf(vs[2*jp+1], sA[cb+2*jp+1], sC[cb+2*jp+1]), 0.0f);
            __half h0, l0, h1, l1;
            split2h(v0, h0, l0); split2h(v1, h1, l1);
            hp[jp] = (uint32_t)__half_as_ushort(h0) |
                     ((uint32_t)__half_as_ushort(h1) << 16);
            lp[jp] = (uint32_t)__half_as_ushort(l0) |
                     ((uint32_t)__half_as_ushort(l1) << 16);
        }
        *(uint4*)(dst + (r*ST + q*8)*2)           = make_uint4(hp[0], hp[1], hp[2], hp[3]);
        *(uint4*)(dst + OFF_ALO + (r*ST + q*8)*2) = make_uint4(lp[0], lp[1], lp[2], lp[3]);
    }
}

__device__ __forceinline__ void compute_chunk(const char* smc, int wn, int wo,
                                              int g, int m, float acc[4][8][4]) {
#pragma unroll
    for (int ks = 0; ks < 2; ks++) {
        int cb = ks*16 + 2*m;
        uint32_t ah[4][4], al[4][4];
#pragma unroll
        for (int i = 0; i < 4; i++) {
            int r0 = wn*64 + i*16 + g;
            ah[i][0] = *(const uint32_t*)(smc + (r0*ST + cb)*2);
            ah[i][1] = *(const uint32_t*)(smc + ((r0+8)*ST + cb)*2);
            ah[i][2] = *(const uint32_t*)(smc + (r0*ST + cb + 8)*2);
            ah[i][3] = *(const uint32_t*)(smc + ((r0+8)*ST + cb + 8)*2);
            al[i][0] = *(const uint32_t*)(smc + OFF_ALO + (r0*ST + cb)*2);
            al[i][1] = *(const uint32_t*)(smc + OFF_ALO + ((r0+8)*ST + cb)*2);
            al[i][2] = *(const uint32_t*)(smc + OFF_ALO + (r0*ST + cb + 8)*2);
            al[i][3] = *(const uint32_t*)(smc + OFF_ALO + ((r0+8)*ST + cb + 8)*2);
        }
#pragma unroll
        for (int j = 0; j < 8; j++) {
            int ro = wo*64 + j*8 + g;
            uint32_t bh0 = *(const uint32_t*)(smc + OFF_WHI + (ro*ST + cb)*2);
            uint32_t bh1 = *(const uint32_t*)(smc + OFF_WHI + (ro*ST + cb + 8)*2);
#pragma unroll
            for (int i = 0; i < 4; i++) {
                mma16816h(acc[i][j], ah[i][0], ah[i][1], ah[i][2], ah[i][3], bh0, bh1);
                mma16816h(acc[i][j], al[i][0], al[i][1], al[i][2], al[i][3], bh0, bh1);
            }
        }
    }
}

template<int LAYER>
__global__ void __launch_bounds__(256, 1) gemm_kernel() {
    const __half* Wh = LAYER ? d_W2h : d_W1h;
    const int KT  = LAYER ? KT2 : KT1;
    const int nKB = KT >> 5;

    extern __shared__ char sm[];
    int tid = threadIdx.x, lane = tid & 31, wid = tid >> 5;
    int g = lane >> 2, m = lane & 3;
    int wn = wid & 1, wo = wid >> 1;
    int nbase = blockIdx.x * 128;

    float* sA = (float*)(sm + SM_A1);
    float* sC = (float*)(sm + SM_C1);
    if (LAYER) { sA[tid] = d_aA[tid]; sC[tid] = d_cA[tid]; }

    float acc[4][8][4];
#pragma unroll
    for (int i = 0; i < 4; i++)
#pragma unroll
        for (int j = 0; j < 8; j++)
#pragma unroll
            for (int e = 0; e < 4; e++) acc[i][j][e] = 0.0f;

    float4 rg[4];
    if (LAYER) {
        __syncthreads();
        prefA1(rg, nbase, 0, tid);
        stageA1(sm, rg, 0, tid, sA, sC);
    } else {
        stageA0(sm, nbase, 0, tid);
    }
    stageW(sm, Wh, KT, 0, tid);
    CP_COMMIT();
    if (LAYER) prefA1(rg, nbase, 1, tid);

    for (int kb = 0; kb < nKB; kb++) {
        char* cur = sm + (kb % 3) * BUFSZ;
        char* nxt = sm + ((kb + 1) % 3) * BUFSZ;
        if (kb + 1 < nKB) {
            if (LAYER) {
                stageA1(nxt, rg, kb + 1, tid, sA, sC);
                if (kb + 2 < nKB) prefA1(rg, nbase, kb + 2, tid);
            } else {
                stageA0(nxt, nbase, kb + 1, tid);
            }
            stageW(nxt, Wh, KT, kb + 1, tid);
            CP_COMMIT();
            CP_WAIT1();
        } else {
            CP_WAIT0();
        }
        __syncthreads();
        compute_chunk(cur, wn, wo, g, m, acc);
    }
    __syncthreads();

    // ---------------- epilogue -------------------------------------------------
    float* ys = (float*)(sm + SM_YS);
    float* qs = (float*)(sm + SM_QS);
    ys[tid] = 0.0f; qs[tid] = 0.0f;
    __syncthreads();

    float sc[8][2], qc[8][2];
#pragma unroll
    for (int j = 0; j < 8; j++) { sc[j][0]=sc[j][1]=qc[j][0]=qc[j][1]=0.0f; }

#pragma unroll
    for (int i = 0; i < 4; i++) {
        int r0 = nbase + wn*64 + i*16 + g;
#pragma unroll
        for (int j = 0; j < 8; j++) {
            int col = wo*64 + j*8 + 2*m;
            float v0 = acc[i][j][0], v1 = acc[i][j][1];
            float v2 = acc[i][j][2], v3 = acc[i][j][3];
            if (!LAYER) {
                *(float2*)(d_Y1 + (size_t)r0*256 + col)     = make_float2(v0, v1);
                *(float2*)(d_Y1 + (size_t)(r0+8)*256 + col) = make_float2(v2, v3);
            } else {
                float mxa = fmaxf(v0, v2), mxb = fmaxf(v1, v3);
                float mna = fminf(v0, v2), mnb = fminf(v1, v3);
#pragma unroll
                for (int off = 4; off < 32; off <<= 1) {
                    mxa = fmaxf(mxa, __shfl_xor_sync(0xFFFFFFFFu, mxa, off));
                    mxb = fmaxf(mxb, __shfl_xor_sync(0xFFFFFFFFu, mxb, off));
                    mna = fminf(mna, __shfl_xor_sync(0xFFFFFFFFu, mna, off));
                    mnb = fminf(mnb, __shfl_xor_sync(0xFFFFFFFFu, mnb, off));
                }
                if (g == 0) {
                    int q = blockIdx.x*8 + wn*4 + i;
                    *(float2*)(d_qmax + (size_t)q*256 + col) = make_float2(mxa, mxb);
                    *(float2*)(d_qmin + (size_t)q*256 + col) = make_float2(mna, mnb);
                }
            }
            sc[j][0] += v0 + v2;       sc[j][1] += v1 + v3;
            qc[j][0] += v0*v0 + v2*v2; qc[j][1] += v1*v1 + v3*v3;
        }
    }
#pragma unroll
    for (int j = 0; j < 8; j++)
#pragma unroll
        for (int e = 0; e < 2; e++) {
#pragma unroll
            for (int off = 4; off < 32; off <<= 1) {
                sc[j][e] += __shfl_xor_sync(0xFFFFFFFFu, sc[j][e], off);
                qc[j][e] += __shfl_xor_sync(0xFFFFFFFFu, qc[j][e], off);
            }
        }
    if (wn == 0 && lane < 4) {
#pragma unroll
        for (int j = 0; j < 8; j++) {
            int col = wo*64 + j*8 + 2*lane;
            ys[col] = sc[j][0];   ys[col+1] = sc[j][1];
            qs[col] = qc[j][0];   qs[col+1] = qc[j][1];
        }
    }
    __syncthreads();
    if (wn == 1 && lane < 4) {
#pragma unroll
        for (int j = 0; j < 8; j++) {
            int col = wo*64 + j*8 + 2*lane;
            ys[col] += sc[j][0];  ys[col+1] += sc[j][1];
            qs[col] += qc[j][0];  qs[col+1] += qc[j][1];
        }
    }
    __syncthreads();
    d_psY[(size_t)tid*NTILES + blockIdx.x] = ys[tid];
    d_psQ[(size_t)tid*NTILES + blockIdx.x] = qs[tid];
}

// ---------------- BN stats finalize (256 blocks, coalesced) --------------------
__global__ void __launch_bounds__(256) stats_final(int layer,
                                                   const float* __restrict__ g,
                                                   const float* __restrict__ bt) {
    int o = blockIdx.x, t = threadIdx.x;
    float s = 0.0f, q = 0.0f;
    for (int i = t; i < NTILES; i += 256) {
        s += d_psY[(size_t)o*NTILES + i];
        q += d_psQ[(size_t)o*NTILES + i];
    }
    __shared__ float ss[8], sq[8];
#pragma unroll
    for (int off = 16; off > 0; off >>= 1) {
        s += __shfl_down_sync(0xFFFFFFFFu, s, off);
        q += __shfl_down_sync(0xFFFFFFFFu, q, off);
    }
    if ((t & 31) == 0) { ss[t >> 5] = s; sq[t >> 5] = q; }
    __syncthreads();
    if (t == 0) {
        float S = 0.0f, Q = 0.0f;
#pragma unroll
        for (int i = 0; i < 8; i++) { S += ss[i]; Q += sq[i]; }
        float mean = S * (1.0f / NT);
        float var  = Q * (1.0f / NT) - mean*mean;
        float av = rsqrtf(var + 1e-5f) * g[o];
        d_aA[layer*256 + o] = av;
        d_cA[layer*256 + o] = bt[o] - mean * av;   // bias-free (cancels in BN)
    }
}

// ----------- final: pick max/min by sign(a2), affine + relu --------------------
__global__ void __launch_bounds__(256) final_kernel(float* __restrict__ out) {
    size_t idx = (size_t)blockIdx.x * 256 + threadIdx.x;
    int o = threadIdx.x;
    float a = d_aA[256 + o], c = d_cA[256 + o];
    float v = (a >= 0.0f) ? d_qmax[idx] : d_qmin[idx];
    out[OUT_XYZ + idx] = fmaxf(fmaf(v, a, c), 0.0f);
}

// ------------------------------- launch ----------------------------------------
extern "C" void kernel_launch(void* const* d_in, const int* in_sizes, int n_in,
                              void* d_out, int out_size) {
    const float* xyz    = (const float*)d_in[0];
    const float* points = (const float*)d_in[1];
    const float* W1  = (const float*)d_in[2];
    const float* g1  = (const float*)d_in[4];
    const float* bt1 = (const float*)d_in[5];
    const float* W2  = (const float*)d_in[6];
    const float* g2  = (const float*)d_in[8];
    const float* bt2 = (const float*)d_in[9];
    float* out = (float*)d_out;

    cudaFuncSetAttribute(gemm_kernel<0>, cudaFuncAttributeMaxDynamicSharedMemorySize, SM_TOT);
    cudaFuncSetAttribute(gemm_kernel<1>, cudaFuncAttributeMaxDynamicSharedMemorySize, SM_TOT);

    // fps stays the 4th launch -> ncu verifies the merge-reduction delta
    prep1a_kernel<<<96, 256>>>(W1);
    prep1b_kernel<<<96, 256>>>(W1);
    prep2_kernel<<<256, 256>>>(W2);
    fps_kernel<<<Bq, 512>>>(xyz, out);
    knng_kernel<<<dim3(Sq, Bq), 256>>>(xyz, points);
    gemm_kernel<0><<<NTILES, 256, SM_TOT>>>();
    stats_final<<<256, 256>>>(0, g1, bt1);
    gemm_kernel<1><<<NTILES, 256, SM_TOT>>>();
    stats_final<<<256, 256>>>(1, g2, bt2);
    final_kernel<<<Bq*Sq, 256>>>(out);
}